// round 4
// baseline (speedup 1.0000x reference)
#include <cuda_runtime.h>
#include <math.h>

#define N_NODES 50000
#define E_EDGES 800000
#define E_TOT   (E_EDGES + N_NODES)
#define IN_DIM  512
#define F1      256
#define NH1     4
#define F2      40
#define NEG_SLOPE 0.2f
#define NINF (-__int_as_float(0x7f800000))
#define SCAN_BLOCKS 196   // 196*256 = 50176 >= N_NODES

// ---------------- scratch (static device allocations only) ----------------
__device__ int   g_is64;
__device__ int   g_src[E_EDGES];
__device__ int   g_dst[E_EDGES];
__device__ int   g_deg[N_NODES];
__device__ int   g_bsum[SCAN_BLOCKS];
__device__ int   g_boff[SCAN_BLOCKS];
__device__ int   g_rowstart[N_NODES + 1];
__device__ int   g_cursor[N_NODES];
__device__ int   g_csr[E_TOT];
__device__ float g_h1[(size_t)N_NODES * F1];
__device__ float g_as1[N_NODES * NH1];
__device__ float g_ad1[N_NODES * NH1];
__device__ float g_hmid[(size_t)N_NODES * F1];
__device__ float g_h2[(size_t)N_NODES * F2];
__device__ float g_as2[N_NODES];
__device__ float g_ad2[N_NODES];

// ---------------- helpers ----------------
__device__ __forceinline__ void atomicMaxFloatS(float* addr, float val) {
    if (val >= 0.f) atomicMax((int*)addr, __float_as_int(val));
    else            atomicMin((unsigned int*)addr, __float_as_uint(val));
}
__device__ __forceinline__ float lrelu(float x) { return x > 0.f ? x : NEG_SLOPE * x; }

__device__ __forceinline__ void fma2(unsigned long long& d, unsigned long long a,
                                     unsigned long long b) {
    asm("fma.rn.f32x2 %0, %1, %2, %0;" : "+l"(d) : "l"(a), "l"(b));
}
__device__ __forceinline__ float2 upk2(unsigned long long v) {
    float2 r;
    asm("mov.b64 {%0, %1}, %2;" : "=f"(r.x), "=f"(r.y) : "l"(v));
    return r;
}

// ---------------- edge dtype detect + convert + degree count ----------------
__global__ void k_detect(const int* e32) {
    int allzero = 1;
    for (int i = 1; i < 256; i += 2) if (e32[i] != 0) allzero = 0;
    g_is64 = allzero;
}

__global__ void k_initdeg() {
    int i = blockIdx.x * blockDim.x + threadIdx.x;
    if (i < N_NODES) g_deg[i] = 1;  // self loop
}

__global__ void k_convert_count(const void* eptr) {
    int i = blockIdx.x * blockDim.x + threadIdx.x;
    if (i >= E_EDGES) return;
    int s, d;
    if (g_is64) {
        const long long* e = (const long long*)eptr;
        s = (int)e[i];
        d = (int)e[E_EDGES + i];
    } else {
        const int* e = (const int*)eptr;
        s = e[i];
        d = e[E_EDGES + i];
    }
    g_src[i] = s;
    g_dst[i] = d;
    atomicAdd(&g_deg[d], 1);
}

// ---------------- parallel 3-phase scan ----------------
__global__ void k_bsum() {
    __shared__ int sh[256];
    const int b = blockIdx.x, t = threadIdx.x;
    const int i = b * 256 + t;
    sh[t] = (i < N_NODES) ? g_deg[i] : 0;
    __syncthreads();
#pragma unroll
    for (int off = 128; off; off >>= 1) {
        if (t < off) sh[t] += sh[t + off];
        __syncthreads();
    }
    if (t == 0) g_bsum[b] = sh[0];
}

__global__ void k_bscan() {
    __shared__ int sh[256];
    const int t = threadIdx.x;
    int mine = (t < SCAN_BLOCKS) ? g_bsum[t] : 0;
    sh[t] = mine;
    __syncthreads();
#pragma unroll
    for (int off = 1; off < 256; off <<= 1) {
        int v = (t >= off) ? sh[t - off] : 0;
        __syncthreads();
        sh[t] += v;
        __syncthreads();
    }
    if (t < SCAN_BLOCKS) g_boff[t] = sh[t] - mine;  // exclusive prefix
}

__global__ void k_rowstart() {
    __shared__ int sh[256];
    const int b = blockIdx.x, t = threadIdx.x;
    const int i = b * 256 + t;
    const int v = (i < N_NODES) ? g_deg[i] : 0;
    sh[t] = v;
    __syncthreads();
#pragma unroll
    for (int off = 1; off < 256; off <<= 1) {
        int u = (t >= off) ? sh[t - off] : 0;
        __syncthreads();
        sh[t] += u;
        __syncthreads();
    }
    const int excl = g_boff[b] + sh[t] - v;
    if (i < N_NODES) {
        g_rowstart[i] = excl;
        g_cursor[i]   = excl;
        if (i == N_NODES - 1) g_rowstart[N_NODES] = excl + v;
    }
}

__global__ void k_scatter() {
    int i = blockIdx.x * blockDim.x + threadIdx.x;
    if (i >= E_TOT) return;
    int s, d;
    if (i < E_EDGES) { s = g_src[i]; d = g_dst[i]; }
    else             { s = d = i - E_EDGES; }
    int pos = atomicAdd(&g_cursor[d], 1);
    g_csr[pos] = s;
}

// ---------------- GEMM1: h1 = x @ W1   [50000,512]x[512,256] ----------------
// Double-buffered 128x128x16, 8x8/thread, pure FFMA2 inner loop (no pack MOVs):
// A is stored DUPLICATED ([v,v] pairs) so the broadcast operand is one LDS.64.
#define BM 128
#define BN 128
#define BK 16
#define APITCH 264   // 2*128 + 8 pad floats; 1056B row stride (16B-aligned)
__global__ __launch_bounds__(256, 2) void k_gemm1(const float* __restrict__ x,
                                                  const float* __restrict__ W) {
    __shared__ float Asd[2][BK][APITCH];
    __shared__ float Bs[2][BK][BN];
    const int bm = blockIdx.y * BM, bn = blockIdx.x * BN;
    const int t = threadIdx.x;
    const int tx = t & 15, ty = t >> 4;
    const int arow0 = t >> 2;           // 0..63 (+64 for second)
    const int akv   = (t & 3) * 4;      // k offset within tile
    const int brow0 = t >> 5;           // 0..7 (+8 for second)
    const int bcv   = (t & 31) * 4;     // col offset

    unsigned long long acc[8][4];
#pragma unroll
    for (int i = 0; i < 8; i++)
#pragma unroll
        for (int j = 0; j < 4; j++) acc[i][j] = 0ULL;

    float4 pa[2], pb[2];
#pragma unroll
    for (int r = 0; r < 2; r++) {
        int row = arow0 + 64 * r;
        int gr = bm + row;
        pa[r] = make_float4(0.f, 0.f, 0.f, 0.f);
        if (gr < N_NODES) pa[r] = *(const float4*)&x[(size_t)gr * IN_DIM + akv];
        pb[r] = *(const float4*)&W[(size_t)(brow0 + 8 * r) * F1 + bn + bcv];
    }
#pragma unroll
    for (int r = 0; r < 2; r++) {
        int row2 = (arow0 + 64 * r) * 2;
        *(float2*)&Asd[0][akv + 0][row2] = make_float2(pa[r].x, pa[r].x);
        *(float2*)&Asd[0][akv + 1][row2] = make_float2(pa[r].y, pa[r].y);
        *(float2*)&Asd[0][akv + 2][row2] = make_float2(pa[r].z, pa[r].z);
        *(float2*)&Asd[0][akv + 3][row2] = make_float2(pa[r].w, pa[r].w);
        *(float4*)&Bs[0][brow0 + 8 * r][bcv] = pb[r];
    }
    __syncthreads();

    int buf = 0;
    for (int k0 = 0; k0 < IN_DIM; k0 += BK) {
        const bool has_next = (k0 + BK) < IN_DIM;
        if (has_next) {
#pragma unroll
            for (int r = 0; r < 2; r++) {
                int row = arow0 + 64 * r;
                int gr = bm + row;
                pa[r] = make_float4(0.f, 0.f, 0.f, 0.f);
                if (gr < N_NODES)
                    pa[r] = *(const float4*)&x[(size_t)gr * IN_DIM + k0 + BK + akv];
                pb[r] = *(const float4*)&W[(size_t)(k0 + BK + brow0 + 8 * r) * F1 + bn + bcv];
            }
        }
#pragma unroll
        for (int kk = 0; kk < BK; kk++) {
            unsigned long long aa[8], B2[4];
#pragma unroll
            for (int j = 0; j < 4; j++)
                B2[j] = *(const unsigned long long*)&Bs[buf][kk][tx * 8 + 2 * j];
#pragma unroll
            for (int i = 0; i < 8; i++)
                aa[i] = *(const unsigned long long*)&Asd[buf][kk][(ty * 8 + i) * 2];
#pragma unroll
            for (int i = 0; i < 8; i++)
#pragma unroll
                for (int j = 0; j < 4; j++) fma2(acc[i][j], aa[i], B2[j]);
        }
        if (has_next) {
#pragma unroll
            for (int r = 0; r < 2; r++) {
                int row2 = (arow0 + 64 * r) * 2;
                *(float2*)&Asd[buf ^ 1][akv + 0][row2] = make_float2(pa[r].x, pa[r].x);
                *(float2*)&Asd[buf ^ 1][akv + 1][row2] = make_float2(pa[r].y, pa[r].y);
                *(float2*)&Asd[buf ^ 1][akv + 2][row2] = make_float2(pa[r].z, pa[r].z);
                *(float2*)&Asd[buf ^ 1][akv + 3][row2] = make_float2(pa[r].w, pa[r].w);
                *(float4*)&Bs[buf ^ 1][brow0 + 8 * r][bcv] = pb[r];
            }
            __syncthreads();
            buf ^= 1;
        }
    }

#pragma unroll
    for (int i = 0; i < 8; i++) {
        int gr = bm + ty * 8 + i;
        if (gr < N_NODES) {
            float2 c0 = upk2(acc[i][0]), c1 = upk2(acc[i][1]);
            float2 c2 = upk2(acc[i][2]), c3 = upk2(acc[i][3]);
            *(float4*)&g_h1[(size_t)gr * F1 + bn + tx * 8]     = make_float4(c0.x, c0.y, c1.x, c1.y);
            *(float4*)&g_h1[(size_t)gr * F1 + bn + tx * 8 + 4] = make_float4(c2.x, c2.y, c3.x, c3.y);
        }
    }
}

// ---------------- attention coefficients layer 1 (warp per node) ----------------
__global__ void k_asd1(const float* __restrict__ atts, const float* __restrict__ attd) {
    int node = blockIdx.x * 8 + (threadIdx.x >> 5);
    int lane = threadIdx.x & 31;
    if (node >= N_NODES) return;
    const float* hr = &g_h1[(size_t)node * F1];
    float4 h1v = *(const float4*)&hr[lane * 4];
    float4 h2v = *(const float4*)&hr[128 + lane * 4];
    float4 sa = *(const float4*)&atts[lane * 4];
    float4 sb = *(const float4*)&atts[128 + lane * 4];
    float4 da = *(const float4*)&attd[lane * 4];
    float4 db = *(const float4*)&attd[128 + lane * 4];
    float ps1 = h1v.x * sa.x + h1v.y * sa.y + h1v.z * sa.z + h1v.w * sa.w;
    float pd1 = h1v.x * da.x + h1v.y * da.y + h1v.z * da.z + h1v.w * da.w;
    float ps2 = h2v.x * sb.x + h2v.y * sb.y + h2v.z * sb.z + h2v.w * sb.w;
    float pd2 = h2v.x * db.x + h2v.y * db.y + h2v.z * db.z + h2v.w * db.w;
#pragma unroll
    for (int off = 8; off; off >>= 1) {
        ps1 += __shfl_down_sync(0xffffffffu, ps1, off);
        pd1 += __shfl_down_sync(0xffffffffu, pd1, off);
        ps2 += __shfl_down_sync(0xffffffffu, ps2, off);
        pd2 += __shfl_down_sync(0xffffffffu, pd2, off);
    }
    if (lane == 0) {
        g_as1[node * 4 + 0] = ps1; g_ad1[node * 4 + 0] = pd1;
        g_as1[node * 4 + 2] = ps2; g_ad1[node * 4 + 2] = pd2;
    }
    if (lane == 16) {
        g_as1[node * 4 + 1] = ps1; g_ad1[node * 4 + 1] = pd1;
        g_as1[node * 4 + 3] = ps2; g_ad1[node * 4 + 3] = pd2;
    }
}

// ---------------- layer-1 aggregation: block per dst, fused bias+elu ----------------
#define CHUNK 512
__global__ __launch_bounds__(256) void k_agg1(const float* __restrict__ b1) {
    const int dst = blockIdx.x;
    const int t = threadIdx.x;
    const int start = g_rowstart[dst];
    const int end = g_rowstart[dst + 1];
    __shared__ float sm[NH1], ss[NH1];
    __shared__ float sal[CHUNK][NH1];
    __shared__ int   ssrc[CHUNK];
    float adv[NH1];
#pragma unroll
    for (int h = 0; h < NH1; h++) adv[h] = g_ad1[dst * 4 + h];
    if (t < NH1) { sm[t] = NINF; ss[t] = 0.f; }
    __syncthreads();

    float lm[NH1] = {NINF, NINF, NINF, NINF};
    for (int i = start + t; i < end; i += 256) {
        int s = g_csr[i];
#pragma unroll
        for (int h = 0; h < NH1; h++)
            lm[h] = fmaxf(lm[h], lrelu(g_as1[s * 4 + h] + adv[h]));
    }
#pragma unroll
    for (int h = 0; h < NH1; h++) atomicMaxFloatS(&sm[h], lm[h]);
    __syncthreads();
    float mx[NH1];
#pragma unroll
    for (int h = 0; h < NH1; h++) mx[h] = sm[h];

    float lsum[NH1] = {0.f, 0.f, 0.f, 0.f};
    for (int i = start + t; i < end; i += 256) {
        int s = g_csr[i];
#pragma unroll
        for (int h = 0; h < NH1; h++)
            lsum[h] += expf(lrelu(g_as1[s * 4 + h] + adv[h]) - mx[h]);
    }
#pragma unroll
    for (int h = 0; h < NH1; h++) atomicAdd(&ss[h], lsum[h]);
    __syncthreads();
    float inv[NH1];
#pragma unroll
    for (int h = 0; h < NH1; h++) inv[h] = 1.f / (ss[h] + 1e-16f);

    const int hh = t >> 6;
    float acc = 0.f;
    for (int base = start; base < end; base += CHUNK) {
        int cnt = min(CHUNK, end - base);
        __syncthreads();
        for (int i = t; i < cnt; i += 256) {
            int s = g_csr[base + i];
            ssrc[i] = s;
#pragma unroll
            for (int h = 0; h < NH1; h++)
                sal[i][h] = expf(lrelu(g_as1[s * 4 + h] + adv[h]) - mx[h]) * inv[h];
        }
        __syncthreads();
#pragma unroll 4
        for (int k = 0; k < cnt; k++)
            acc = fmaf(sal[k][hh], g_h1[(size_t)ssrc[k] * F1 + t], acc);
    }
    float v = acc + b1[t];
    g_hmid[(size_t)dst * F1 + t] = v > 0.f ? v : expm1f(v);  // fused elu
}

// ---------------- GEMM2: h2 = hmid @ W2  [50000,256]x[256,40] ----------------
#define BM2 128
#define BK2 32
__global__ __launch_bounds__(256) void k_gemm2(const float* __restrict__ W2) {
    __shared__ float As2[BM2][BK2 + 4];
    __shared__ float Ws[BK2][F2];
    const int bm = blockIdx.x * BM2;
    const int t = threadIdx.x;
    const int tx = t & 7;
    const int ty = t >> 3;
    float acc[4][5];
#pragma unroll
    for (int i = 0; i < 4; i++)
#pragma unroll
        for (int j = 0; j < 5; j++) acc[i][j] = 0.f;

    for (int k0 = 0; k0 < F1; k0 += BK2) {
#pragma unroll
        for (int r = 0; r < 4; r++) {
            int f = t + r * 256;
            int row = f >> 3;
            int cv = (f & 7) * 4;
            float4 v = make_float4(0.f, 0.f, 0.f, 0.f);
            int gr = bm + row;
            if (gr < N_NODES) v = *(const float4*)&g_hmid[(size_t)gr * F1 + k0 + cv];
            *(float4*)&As2[row][cv] = v;
        }
        for (int idx = t; idx < BK2 * F2; idx += 256) {
            int r = idx / F2, c = idx % F2;
            Ws[r][c] = W2[(size_t)(k0 + r) * F2 + c];
        }
        __syncthreads();
#pragma unroll
        for (int kk = 0; kk < BK2; kk++) {
            float a[4], b[5];
#pragma unroll
            for (int i = 0; i < 4; i++) a[i] = As2[ty * 4 + i][kk];
#pragma unroll
            for (int j = 0; j < 5; j++) b[j] = Ws[kk][tx * 5 + j];
#pragma unroll
            for (int i = 0; i < 4; i++)
#pragma unroll
                for (int j = 0; j < 5; j++) acc[i][j] = fmaf(a[i], b[j], acc[i][j]);
        }
        __syncthreads();
    }
#pragma unroll
    for (int i = 0; i < 4; i++) {
        int gr = bm + ty * 4 + i;
        if (gr < N_NODES)
#pragma unroll
            for (int j = 0; j < 5; j++)
                g_h2[(size_t)gr * F2 + tx * 5 + j] = acc[i][j];
    }
}

// ---------------- attention coefficients layer 2 (warp per node) ----------------
__global__ void k_asd2(const float* __restrict__ atts, const float* __restrict__ attd) {
    int node = blockIdx.x * 8 + (threadIdx.x >> 5);
    int lane = threadIdx.x & 31;
    if (node >= N_NODES) return;
    const float* hr = &g_h2[(size_t)node * F2];
    float h0 = hr[lane];
    float vs = h0 * atts[lane];
    float vd = h0 * attd[lane];
    if (lane < 8) {
        float h1v = hr[32 + lane];
        vs += h1v * atts[32 + lane];
        vd += h1v * attd[32 + lane];
    }
#pragma unroll
    for (int off = 16; off; off >>= 1) {
        vs += __shfl_down_sync(0xffffffffu, vs, off);
        vd += __shfl_down_sync(0xffffffffu, vd, off);
    }
    if (lane == 0) { g_as2[node] = vs; g_ad2[node] = vd; }
}

// ---------------- layer-2 aggregation + bias + log_softmax ----------------
#define CHUNK2 256
__global__ __launch_bounds__(64) void k_agg2(const float* __restrict__ b2,
                                             float* __restrict__ out) {
    const int dst = blockIdx.x;
    const int t = threadIdx.x;
    const int start = g_rowstart[dst];
    const int end = g_rowstart[dst + 1];
    __shared__ float sal[CHUNK2];
    __shared__ int   ssrc[CHUNK2];
    __shared__ float sm, ssum, slog;
    __shared__ float sv[64];
    const float adv = g_ad2[dst];
    if (t == 0) { sm = NINF; ssum = 0.f; }
    __syncthreads();

    float lm = NINF;
    for (int i = start + t; i < end; i += 64)
        lm = fmaxf(lm, lrelu(g_as2[g_csr[i]] + adv));
    atomicMaxFloatS(&sm, lm);
    __syncthreads();
    const float mx = sm;

    float ls = 0.f;
    for (int i = start + t; i < end; i += 64)
        ls += expf(lrelu(g_as2[g_csr[i]] + adv) - mx);
    atomicAdd(&ssum, ls);
    __syncthreads();
    const float inv = 1.f / (ssum + 1e-16f);

    float acc = 0.f;
    for (int base = start; base < end; base += CHUNK2) {
        int cnt = min(CHUNK2, end - base);
        __syncthreads();
        for (int i = t; i < cnt; i += 64) {
            int s = g_csr[base + i];
            ssrc[i] = s;
            sal[i] = expf(lrelu(g_as2[s] + adv) - mx) * inv;
        }
        __syncthreads();
        if (t < F2) {
#pragma unroll 4
            for (int k = 0; k < cnt; k++)
                acc = fmaf(sal[k], g_h2[(size_t)ssrc[k] * F2 + t], acc);
        }
    }
    sv[t] = (t < F2) ? acc + b2[t] : NINF;
    __syncthreads();
    if (t == 0) {
        float m2 = NINF;
        for (int i = 0; i < F2; i++) m2 = fmaxf(m2, sv[i]);
        float se = 0.f;
        for (int i = 0; i < F2; i++) se += expf(sv[i] - m2);
        sm = m2;
        slog = logf(se);
    }
    __syncthreads();
    if (t < F2) out[(size_t)dst * F2 + t] = sv[t] - sm - slog;
}

// ---------------- launch ----------------
extern "C" void kernel_launch(void* const* d_in, const int* in_sizes, int n_in,
                              void* d_out, int out_size) {
    const float* x   = (const float*)d_in[0];
    const void*  ei  = d_in[1];
    const float* W1  = (const float*)d_in[2];
    const float* as1 = (const float*)d_in[3];
    const float* ad1 = (const float*)d_in[4];
    const float* b1  = (const float*)d_in[5];
    const float* W2  = (const float*)d_in[6];
    const float* as2 = (const float*)d_in[7];
    const float* ad2 = (const float*)d_in[8];
    const float* b2  = (const float*)d_in[9];
    float* out = (float*)d_out;

    k_detect<<<1, 1>>>((const int*)ei);                       // #1
    k_initdeg<<<(N_NODES + 255) / 256, 256>>>();              // #2
    k_convert_count<<<(E_EDGES + 255) / 256, 256>>>(ei);      // #3
    dim3 g1(F1 / BN, (N_NODES + BM - 1) / BM);
    k_gemm1<<<g1, 256>>>(x, W1);                              // #4  <- ncu captures this
    k_bsum<<<SCAN_BLOCKS, 256>>>();                           // #5
    k_bscan<<<1, 256>>>();                                    // #6
    k_rowstart<<<SCAN_BLOCKS, 256>>>();                       // #7
    k_scatter<<<(E_TOT + 255) / 256, 256>>>();                // #8
    k_asd1<<<(N_NODES + 7) / 8, 256>>>(as1, ad1);
    k_agg1<<<N_NODES, 256>>>(b1);
    k_gemm2<<<(N_NODES + BM2 - 1) / BM2, 256>>>(W2);
    k_asd2<<<(N_NODES + 7) / 8, 256>>>(as2, ad2);
    k_agg2<<<N_NODES, 64>>>(b2, out);
}

// round 5
// speedup vs baseline: 1.0668x; 1.0668x over previous
#include <cuda_runtime.h>
#include <math.h>

#define N_NODES 50000
#define E_EDGES 800000
#define E_TOT   (E_EDGES + N_NODES)
#define IN_DIM  512
#define F1      256
#define NH1     4
#define F2      40
#define NEG_SLOPE 0.2f
#define NINF (-__int_as_float(0x7f800000))
#define SCAN_BLOCKS 196   // 196*256 = 50176 >= N_NODES

// ---------------- scratch (static device allocations only) ----------------
__device__ int   g_is64;
__device__ int   g_src[E_EDGES];
__device__ int   g_dst[E_EDGES];
__device__ int   g_deg[N_NODES];
__device__ int   g_bsum[SCAN_BLOCKS];
__device__ int   g_boff[SCAN_BLOCKS];
__device__ int   g_rowstart[N_NODES + 1];
__device__ int   g_cursor[N_NODES];
__device__ int   g_csr[E_TOT];
__device__ float g_h1[(size_t)N_NODES * F1];
__device__ float g_as1[N_NODES * NH1];
__device__ float g_ad1[N_NODES * NH1];
__device__ float g_hmid[(size_t)N_NODES * F1];
__device__ float g_h2[(size_t)N_NODES * F2];
__device__ float g_as2[N_NODES];
__device__ float g_ad2[N_NODES];

// ---------------- helpers ----------------
__device__ __forceinline__ void atomicMaxFloatS(float* addr, float val) {
    if (val >= 0.f) atomicMax((int*)addr, __float_as_int(val));
    else            atomicMin((unsigned int*)addr, __float_as_uint(val));
}
__device__ __forceinline__ float lrelu(float x) { return x > 0.f ? x : NEG_SLOPE * x; }

__device__ __forceinline__ unsigned long long pk2(float lo, float hi) {
    unsigned long long r;
    asm("mov.b64 %0, {%1, %2};" : "=l"(r) : "f"(lo), "f"(hi));
    return r;
}
__device__ __forceinline__ void fma2(unsigned long long& d, unsigned long long a,
                                     unsigned long long b) {
    asm("fma.rn.f32x2 %0, %1, %2, %0;" : "+l"(d) : "l"(a), "l"(b));
}
__device__ __forceinline__ float2 upk2(unsigned long long v) {
    float2 r;
    asm("mov.b64 {%0, %1}, %2;" : "=f"(r.x), "=f"(r.y) : "l"(v));
    return r;
}

// ---------------- init: self-loop degree + edge dtype detect ----------------
__global__ void k_init(const int* e32) {
    int i = blockIdx.x * blockDim.x + threadIdx.x;
    if (i < N_NODES) g_deg[i] = 1;  // self loop
    if (i == 0) {
        int allzero = 1;
        for (int j = 1; j < 256; j += 2) if (e32[j] != 0) allzero = 0;
        g_is64 = allzero;
    }
}

__global__ void k_convert_count(const void* eptr) {
    int i = blockIdx.x * blockDim.x + threadIdx.x;
    if (i >= E_EDGES) return;
    int s, d;
    if (g_is64) {
        const long long* e = (const long long*)eptr;
        s = (int)e[i];
        d = (int)e[E_EDGES + i];
    } else {
        const int* e = (const int*)eptr;
        s = e[i];
        d = e[E_EDGES + i];
    }
    g_src[i] = s;
    g_dst[i] = d;
    atomicAdd(&g_deg[d], 1);
}

// ---------------- parallel 3-phase scan ----------------
__global__ void k_bsum() {
    __shared__ int sh[256];
    const int b = blockIdx.x, t = threadIdx.x;
    const int i = b * 256 + t;
    sh[t] = (i < N_NODES) ? g_deg[i] : 0;
    __syncthreads();
#pragma unroll
    for (int off = 128; off; off >>= 1) {
        if (t < off) sh[t] += sh[t + off];
        __syncthreads();
    }
    if (t == 0) g_bsum[b] = sh[0];
}

__global__ void k_bscan() {
    __shared__ int sh[256];
    const int t = threadIdx.x;
    int mine = (t < SCAN_BLOCKS) ? g_bsum[t] : 0;
    sh[t] = mine;
    __syncthreads();
#pragma unroll
    for (int off = 1; off < 256; off <<= 1) {
        int v = (t >= off) ? sh[t - off] : 0;
        __syncthreads();
        sh[t] += v;
        __syncthreads();
    }
    if (t < SCAN_BLOCKS) g_boff[t] = sh[t] - mine;  // exclusive prefix
}

__global__ void k_rowstart() {
    __shared__ int sh[256];
    const int b = blockIdx.x, t = threadIdx.x;
    const int i = b * 256 + t;
    const int v = (i < N_NODES) ? g_deg[i] : 0;
    sh[t] = v;
    __syncthreads();
#pragma unroll
    for (int off = 1; off < 256; off <<= 1) {
        int u = (t >= off) ? sh[t - off] : 0;
        __syncthreads();
        sh[t] += u;
        __syncthreads();
    }
    const int excl = g_boff[b] + sh[t] - v;
    if (i < N_NODES) {
        g_rowstart[i] = excl;
        g_cursor[i]   = excl;
        if (i == N_NODES - 1) g_rowstart[N_NODES] = excl + v;
    }
}

__global__ void k_scatter() {
    int i = blockIdx.x * blockDim.x + threadIdx.x;
    if (i >= E_TOT) return;
    int s, d;
    if (i < E_EDGES) { s = g_src[i]; d = g_dst[i]; }
    else             { s = d = i - E_EDGES; }
    int pos = atomicAdd(&g_cursor[d], 1);
    g_csr[pos] = s;
}

// ---------------- GEMM1: h1 = x @ W1   [50000,512]x[512,256] ----------------
// Double-buffered 128x128x16, 8x8/thread. Inner loop: 4 LDS.128 + 32 FFMA2.
// B pairs come straight out of the LDS.128 register quad (zero MOVs);
// A broadcast pairs are built with ALU MOVs (hidden under the fma pipe).
#define BM 128
#define BN 128
#define BK 16
#define APAD 132   // row stride 528B (16B aligned)
__global__ __launch_bounds__(256, 2) void k_gemm1(const float* __restrict__ x,
                                                  const float* __restrict__ W) {
    __shared__ float As[2][BK][APAD];   // transposed A tile
    __shared__ float Bs[2][BK][BN];
    const int bm = blockIdx.y * BM, bn = blockIdx.x * BN;
    const int t = threadIdx.x;
    const int tx = t & 15, ty = t >> 4;
    const int arow0 = t >> 2;           // 0..63 (+64 for second)
    const int akv   = (t & 3) * 4;      // k offset within tile
    const int brow0 = t >> 5;           // 0..7 (+8 for second)
    const int bcv   = (t & 31) * 4;     // col offset

    unsigned long long acc[8][4];
#pragma unroll
    for (int i = 0; i < 8; i++)
#pragma unroll
        for (int j = 0; j < 4; j++) acc[i][j] = 0ULL;

    float4 pa[2], pb[2];
#pragma unroll
    for (int r = 0; r < 2; r++) {
        int row = arow0 + 64 * r;
        int gr = bm + row;
        pa[r] = make_float4(0.f, 0.f, 0.f, 0.f);
        if (gr < N_NODES) pa[r] = *(const float4*)&x[(size_t)gr * IN_DIM + akv];
        pb[r] = *(const float4*)&W[(size_t)(brow0 + 8 * r) * F1 + bn + bcv];
    }
#pragma unroll
    for (int r = 0; r < 2; r++) {
        int row = arow0 + 64 * r;
        As[0][akv + 0][row] = pa[r].x;
        As[0][akv + 1][row] = pa[r].y;
        As[0][akv + 2][row] = pa[r].z;
        As[0][akv + 3][row] = pa[r].w;
        *(float4*)&Bs[0][brow0 + 8 * r][bcv] = pb[r];
    }
    __syncthreads();

    int buf = 0;
    for (int k0 = 0; k0 < IN_DIM; k0 += BK) {
        const bool has_next = (k0 + BK) < IN_DIM;
        if (has_next) {
#pragma unroll
            for (int r = 0; r < 2; r++) {
                int row = arow0 + 64 * r;
                int gr = bm + row;
                pa[r] = make_float4(0.f, 0.f, 0.f, 0.f);
                if (gr < N_NODES)
                    pa[r] = *(const float4*)&x[(size_t)gr * IN_DIM + k0 + BK + akv];
                pb[r] = *(const float4*)&W[(size_t)(k0 + BK + brow0 + 8 * r) * F1 + bn + bcv];
            }
        }
#pragma unroll
        for (int kk = 0; kk < BK; kk++) {
            // B: two LDS.128 -> register quads = 4 ready-made f32x2 pairs
            ulonglong2 bv0 = *(const ulonglong2*)&Bs[buf][kk][tx * 8];
            ulonglong2 bv1 = *(const ulonglong2*)&Bs[buf][kk][tx * 8 + 4];
            // A: two LDS.128 broadcast
            float4 a0 = *(const float4*)&As[buf][kk][ty * 8];
            float4 a1 = *(const float4*)&As[buf][kk][ty * 8 + 4];
            float a[8] = {a0.x, a0.y, a0.z, a0.w, a1.x, a1.y, a1.z, a1.w};
#pragma unroll
            for (int i = 0; i < 8; i++) {
                unsigned long long aa = pk2(a[i], a[i]);
                fma2(acc[i][0], aa, bv0.x);
                fma2(acc[i][1], aa, bv0.y);
                fma2(acc[i][2], aa, bv1.x);
                fma2(acc[i][3], aa, bv1.y);
            }
        }
        if (has_next) {
#pragma unroll
            for (int r = 0; r < 2; r++) {
                int row = arow0 + 64 * r;
                As[buf ^ 1][akv + 0][row] = pa[r].x;
                As[buf ^ 1][akv + 1][row] = pa[r].y;
                As[buf ^ 1][akv + 2][row] = pa[r].z;
                As[buf ^ 1][akv + 3][row] = pa[r].w;
                *(float4*)&Bs[buf ^ 1][brow0 + 8 * r][bcv] = pb[r];
            }
            __syncthreads();
            buf ^= 1;
        }
    }

#pragma unroll
    for (int i = 0; i < 8; i++) {
        int gr = bm + ty * 8 + i;
        if (gr < N_NODES) {
            float2 c0 = upk2(acc[i][0]), c1 = upk2(acc[i][1]);
            float2 c2 = upk2(acc[i][2]), c3 = upk2(acc[i][3]);
            *(float4*)&g_h1[(size_t)gr * F1 + bn + tx * 8]     = make_float4(c0.x, c0.y, c1.x, c1.y);
            *(float4*)&g_h1[(size_t)gr * F1 + bn + tx * 8 + 4] = make_float4(c2.x, c2.y, c3.x, c3.y);
        }
    }
}

// ---------------- attention coefficients layer 1 (warp per node) ----------------
__global__ void k_asd1(const float* __restrict__ atts, const float* __restrict__ attd) {
    int node = blockIdx.x * 8 + (threadIdx.x >> 5);
    int lane = threadIdx.x & 31;
    if (node >= N_NODES) return;
    const float* hr = &g_h1[(size_t)node * F1];
    float4 h1v = *(const float4*)&hr[lane * 4];
    float4 h2v = *(const float4*)&hr[128 + lane * 4];
    float4 sa = *(const float4*)&atts[lane * 4];
    float4 sb = *(const float4*)&atts[128 + lane * 4];
    float4 da = *(const float4*)&attd[lane * 4];
    float4 db = *(const float4*)&attd[128 + lane * 4];
    float ps1 = h1v.x * sa.x + h1v.y * sa.y + h1v.z * sa.z + h1v.w * sa.w;
    float pd1 = h1v.x * da.x + h1v.y * da.y + h1v.z * da.z + h1v.w * da.w;
    float ps2 = h2v.x * sb.x + h2v.y * sb.y + h2v.z * sb.z + h2v.w * sb.w;
    float pd2 = h2v.x * db.x + h2v.y * db.y + h2v.z * db.z + h2v.w * db.w;
#pragma unroll
    for (int off = 8; off; off >>= 1) {
        ps1 += __shfl_down_sync(0xffffffffu, ps1, off);
        pd1 += __shfl_down_sync(0xffffffffu, pd1, off);
        ps2 += __shfl_down_sync(0xffffffffu, ps2, off);
        pd2 += __shfl_down_sync(0xffffffffu, pd2, off);
    }
    if (lane == 0) {
        g_as1[node * 4 + 0] = ps1; g_ad1[node * 4 + 0] = pd1;
        g_as1[node * 4 + 2] = ps2; g_ad1[node * 4 + 2] = pd2;
    }
    if (lane == 16) {
        g_as1[node * 4 + 1] = ps1; g_ad1[node * 4 + 1] = pd1;
        g_as1[node * 4 + 3] = ps2; g_ad1[node * 4 + 3] = pd2;
    }
}

// ---------------- layer-1 aggregation: block per dst, fused bias+elu ----------------
#define CHUNK 512
__global__ __launch_bounds__(256) void k_agg1(const float* __restrict__ b1) {
    const int dst = blockIdx.x;
    const int t = threadIdx.x;
    const int start = g_rowstart[dst];
    const int end = g_rowstart[dst + 1];
    __shared__ float sm[NH1], ss[NH1];
    __shared__ float sal[CHUNK][NH1];
    __shared__ int   ssrc[CHUNK];
    float adv[NH1];
#pragma unroll
    for (int h = 0; h < NH1; h++) adv[h] = g_ad1[dst * 4 + h];
    if (t < NH1) { sm[t] = NINF; ss[t] = 0.f; }
    __syncthreads();

    float lm[NH1] = {NINF, NINF, NINF, NINF};
    for (int i = start + t; i < end; i += 256) {
        int s = g_csr[i];
#pragma unroll
        for (int h = 0; h < NH1; h++)
            lm[h] = fmaxf(lm[h], lrelu(g_as1[s * 4 + h] + adv[h]));
    }
#pragma unroll
    for (int h = 0; h < NH1; h++) atomicMaxFloatS(&sm[h], lm[h]);
    __syncthreads();
    float mx[NH1];
#pragma unroll
    for (int h = 0; h < NH1; h++) mx[h] = sm[h];

    float lsum[NH1] = {0.f, 0.f, 0.f, 0.f};
    for (int i = start + t; i < end; i += 256) {
        int s = g_csr[i];
#pragma unroll
        for (int h = 0; h < NH1; h++)
            lsum[h] += expf(lrelu(g_as1[s * 4 + h] + adv[h]) - mx[h]);
    }
#pragma unroll
    for (int h = 0; h < NH1; h++) atomicAdd(&ss[h], lsum[h]);
    __syncthreads();
    float inv[NH1];
#pragma unroll
    for (int h = 0; h < NH1; h++) inv[h] = 1.f / (ss[h] + 1e-16f);

    const int hh = t >> 6;
    float acc = 0.f;
    for (int base = start; base < end; base += CHUNK) {
        int cnt = min(CHUNK, end - base);
        __syncthreads();
        for (int i = t; i < cnt; i += 256) {
            int s = g_csr[base + i];
            ssrc[i] = s;
#pragma unroll
            for (int h = 0; h < NH1; h++)
                sal[i][h] = expf(lrelu(g_as1[s * 4 + h] + adv[h]) - mx[h]) * inv[h];
        }
        __syncthreads();
#pragma unroll 4
        for (int k = 0; k < cnt; k++)
            acc = fmaf(sal[k][hh], g_h1[(size_t)ssrc[k] * F1 + t], acc);
    }
    float v = acc + b1[t];
    g_hmid[(size_t)dst * F1 + t] = v > 0.f ? v : expm1f(v);  // fused elu
}

// ---------------- GEMM2: h2 = hmid @ W2  [50000,256]x[256,40] ----------------
#define BM2 128
#define BK2 32
__global__ __launch_bounds__(256) void k_gemm2(const float* __restrict__ W2) {
    __shared__ float As2[BM2][BK2 + 4];
    __shared__ float Ws[BK2][F2];
    const int bm = blockIdx.x * BM2;
    const int t = threadIdx.x;
    const int tx = t & 7;
    const int ty = t >> 3;
    float acc[4][5];
#pragma unroll
    for (int i = 0; i < 4; i++)
#pragma unroll
        for (int j = 0; j < 5; j++) acc[i][j] = 0.f;

    for (int k0 = 0; k0 < F1; k0 += BK2) {
#pragma unroll
        for (int r = 0; r < 4; r++) {
            int f = t + r * 256;
            int row = f >> 3;
            int cv = (f & 7) * 4;
            float4 v = make_float4(0.f, 0.f, 0.f, 0.f);
            int gr = bm + row;
            if (gr < N_NODES) v = *(const float4*)&g_hmid[(size_t)gr * F1 + k0 + cv];
            *(float4*)&As2[row][cv] = v;
        }
        for (int idx = t; idx < BK2 * F2; idx += 256) {
            int r = idx / F2, c = idx % F2;
            Ws[r][c] = W2[(size_t)(k0 + r) * F2 + c];
        }
        __syncthreads();
#pragma unroll
        for (int kk = 0; kk < BK2; kk++) {
            float a[4], b[5];
#pragma unroll
            for (int i = 0; i < 4; i++) a[i] = As2[ty * 4 + i][kk];
#pragma unroll
            for (int j = 0; j < 5; j++) b[j] = Ws[kk][tx * 5 + j];
#pragma unroll
            for (int i = 0; i < 4; i++)
#pragma unroll
                for (int j = 0; j < 5; j++) acc[i][j] = fmaf(a[i], b[j], acc[i][j]);
        }
        __syncthreads();
    }
#pragma unroll
    for (int i = 0; i < 4; i++) {
        int gr = bm + ty * 4 + i;
        if (gr < N_NODES)
#pragma unroll
            for (int j = 0; j < 5; j++)
                g_h2[(size_t)gr * F2 + tx * 5 + j] = acc[i][j];
    }
}

// ---------------- attention coefficients layer 2 (warp per node) ----------------
__global__ void k_asd2(const float* __restrict__ atts, const float* __restrict__ attd) {
    int node = blockIdx.x * 8 + (threadIdx.x >> 5);
    int lane = threadIdx.x & 31;
    if (node >= N_NODES) return;
    const float* hr = &g_h2[(size_t)node * F2];
    float h0 = hr[lane];
    float vs = h0 * atts[lane];
    float vd = h0 * attd[lane];
    if (lane < 8) {
        float h1v = hr[32 + lane];
        vs += h1v * atts[32 + lane];
        vd += h1v * attd[32 + lane];
    }
#pragma unroll
    for (int off = 16; off; off >>= 1) {
        vs += __shfl_down_sync(0xffffffffu, vs, off);
        vd += __shfl_down_sync(0xffffffffu, vd, off);
    }
    if (lane == 0) { g_as2[node] = vs; g_ad2[node] = vd; }
}

// ---------------- layer-2 aggregation + bias + log_softmax ----------------
#define CHUNK2 256
__global__ __launch_bounds__(64) void k_agg2(const float* __restrict__ b2,
                                             float* __restrict__ out) {
    const int dst = blockIdx.x;
    const int t = threadIdx.x;
    const int start = g_rowstart[dst];
    const int end = g_rowstart[dst + 1];
    __shared__ float sal[CHUNK2];
    __shared__ int   ssrc[CHUNK2];
    __shared__ float sm, ssum, slog;
    __shared__ float sv[64];
    const float adv = g_ad2[dst];
    if (t == 0) { sm = NINF; ssum = 0.f; }
    __syncthreads();

    float lm = NINF;
    for (int i = start + t; i < end; i += 64)
        lm = fmaxf(lm, lrelu(g_as2[g_csr[i]] + adv));
    atomicMaxFloatS(&sm, lm);
    __syncthreads();
    const float mx = sm;

    float ls = 0.f;
    for (int i = start + t; i < end; i += 64)
        ls += expf(lrelu(g_as2[g_csr[i]] + adv) - mx);
    atomicAdd(&ssum, ls);
    __syncthreads();
    const float inv = 1.f / (ssum + 1e-16f);

    float acc = 0.f;
    for (int base = start; base < end; base += CHUNK2) {
        int cnt = min(CHUNK2, end - base);
        __syncthreads();
        for (int i = t; i < cnt; i += 64) {
            int s = g_csr[base + i];
            ssrc[i] = s;
            sal[i] = expf(lrelu(g_as2[s] + adv) - mx) * inv;
        }
        __syncthreads();
        if (t < F2) {
#pragma unroll 4
            for (int k = 0; k < cnt; k++)
                acc = fmaf(sal[k], g_h2[(size_t)ssrc[k] * F2 + t], acc);
        }
    }
    sv[t] = (t < F2) ? acc + b2[t] : NINF;
    __syncthreads();
    if (t == 0) {
        float m2 = NINF;
        for (int i = 0; i < F2; i++) m2 = fmaxf(m2, sv[i]);
        float se = 0.f;
        for (int i = 0; i < F2; i++) se += expf(sv[i] - m2);
        sm = m2;
        slog = logf(se);
    }
    __syncthreads();
    if (t < F2) out[(size_t)dst * F2 + t] = sv[t] - sm - slog;
}

// ---------------- launch ----------------
extern "C" void kernel_launch(void* const* d_in, const int* in_sizes, int n_in,
                              void* d_out, int out_size) {
    const float* x   = (const float*)d_in[0];
    const void*  ei  = d_in[1];
    const float* W1  = (const float*)d_in[2];
    const float* as1 = (const float*)d_in[3];
    const float* ad1 = (const float*)d_in[4];
    const float* b1  = (const float*)d_in[5];
    const float* W2  = (const float*)d_in[6];
    const float* as2 = (const float*)d_in[7];
    const float* ad2 = (const float*)d_in[8];
    const float* b2  = (const float*)d_in[9];
    float* out = (float*)d_out;

    k_init<<<(N_NODES + 255) / 256, 256>>>((const int*)ei);  // #1
    k_convert_count<<<(E_EDGES + 255) / 256, 256>>>(ei);     // #2
    k_bsum<<<SCAN_BLOCKS, 256>>>();                          // #3
    dim3 g1(F1 / BN, (N_NODES + BM - 1) / BM);
    k_gemm1<<<g1, 256>>>(x, W1);                             // #4  <- ncu captures this
    k_bscan<<<1, 256>>>();                                   // #5
    k_rowstart<<<SCAN_BLOCKS, 256>>>();                      // #6
    k_scatter<<<(E_TOT + 255) / 256, 256>>>();               // #7
    k_asd1<<<(N_NODES + 7) / 8, 256>>>(as1, ad1);
    k_agg1<<<N_NODES, 256>>>(b1);
    k_gemm2<<<(N_NODES + BM2 - 1) / BM2, 256>>>(W2);
    k_asd2<<<(N_NODES + 7) / 8, 256>>>(as2, ad2);
    k_agg2<<<N_NODES, 64>>>(b2, out);
}

// round 7
// speedup vs baseline: 1.0857x; 1.0177x over previous
#include <cuda_runtime.h>
#include <math.h>

#define N_NODES 50000
#define E_EDGES 800000
#define E_TOT   (E_EDGES + N_NODES)
#define IN_DIM  512
#define F1      256
#define NH1     4
#define F2      40
#define NEG_SLOPE 0.2f
#define NINF (-__int_as_float(0x7f800000))
#define SCAN_BLOCKS 196   // 196*256 = 50176 >= N_NODES
#define MAXDEG 512        // fast-path degree cap

// ---------------- scratch (static device allocations only) ----------------
__device__ int   g_is64;
__device__ int   g_src[E_EDGES];
__device__ int   g_dst[E_EDGES];
__device__ int   g_deg[N_NODES];
__device__ int   g_bsum[SCAN_BLOCKS];
__device__ int   g_boff[SCAN_BLOCKS];
__device__ int   g_rowstart[N_NODES + 1];
__device__ int   g_cursor[N_NODES];
__device__ int   g_csr[E_TOT];
__device__ __align__(16) float g_h1[(size_t)N_NODES * F1];
__device__ __align__(16) float g_as1[N_NODES * NH1];
__device__ __align__(16) float g_ad1[N_NODES * NH1];
__device__ __align__(16) float g_hmid[(size_t)N_NODES * F1];
__device__ __align__(16) float g_h2[(size_t)N_NODES * F2];
__device__ float g_as2[N_NODES];
__device__ float g_ad2[N_NODES];

// ---------------- helpers ----------------
__device__ __forceinline__ void atomicMaxFloatS(float* addr, float val) {
    if (val >= 0.f) atomicMax((int*)addr, __float_as_int(val));
    else            atomicMin((unsigned int*)addr, __float_as_uint(val));
}
__device__ __forceinline__ float lrelu(float x) { return x > 0.f ? x : NEG_SLOPE * x; }

__device__ __forceinline__ unsigned long long pk2(float lo, float hi) {
    unsigned long long r;
    asm("mov.b64 %0, {%1, %2};" : "=l"(r) : "f"(lo), "f"(hi));
    return r;
}
__device__ __forceinline__ void fma2(unsigned long long& d, unsigned long long a,
                                     unsigned long long b) {
    asm("fma.rn.f32x2 %0, %1, %2, %0;" : "+l"(d) : "l"(a), "l"(b));
}
__device__ __forceinline__ float2 upk2(unsigned long long v) {
    float2 r;
    asm("mov.b64 {%0, %1}, %2;" : "=f"(r.x), "=f"(r.y) : "l"(v));
    return r;
}

// ---------------- init: self-loop degree, zero attn accumulators, dtype detect ----
__global__ void k_init(const int* e32) {
    int i = blockIdx.x * blockDim.x + threadIdx.x;
    if (i < N_NODES) {
        g_deg[i] = 1;  // self loop
        *(float4*)&g_as1[i * 4] = make_float4(0.f, 0.f, 0.f, 0.f);
        *(float4*)&g_ad1[i * 4] = make_float4(0.f, 0.f, 0.f, 0.f);
    }
    if (i == 0) {
        int allzero = 1;
        for (int j = 1; j < 256; j += 2) if (e32[j] != 0) allzero = 0;
        g_is64 = allzero;
    }
}

__global__ void k_convert_count(const void* eptr) {
    int i = blockIdx.x * blockDim.x + threadIdx.x;
    if (i >= E_EDGES) return;
    int s, d;
    if (g_is64) {
        const long long* e = (const long long*)eptr;
        s = (int)e[i];
        d = (int)e[E_EDGES + i];
    } else {
        const int* e = (const int*)eptr;
        s = e[i];
        d = e[E_EDGES + i];
    }
    g_src[i] = s;
    g_dst[i] = d;
    atomicAdd(&g_deg[d], 1);
}

// ---------------- parallel 3-phase scan ----------------
__global__ void k_bsum() {
    __shared__ int sh[256];
    const int b = blockIdx.x, t = threadIdx.x;
    const int i = b * 256 + t;
    sh[t] = (i < N_NODES) ? g_deg[i] : 0;
    __syncthreads();
#pragma unroll
    for (int off = 128; off; off >>= 1) {
        if (t < off) sh[t] += sh[t + off];
        __syncthreads();
    }
    if (t == 0) g_bsum[b] = sh[0];
}

__global__ void k_bscan() {
    __shared__ int sh[256];
    const int t = threadIdx.x;
    int mine = (t < SCAN_BLOCKS) ? g_bsum[t] : 0;
    sh[t] = mine;
    __syncthreads();
#pragma unroll
    for (int off = 1; off < 256; off <<= 1) {
        int v = (t >= off) ? sh[t - off] : 0;
        __syncthreads();
        sh[t] += v;
        __syncthreads();
    }
    if (t < SCAN_BLOCKS) g_boff[t] = sh[t] - mine;  // exclusive prefix
}

__global__ void k_rowstart() {
    __shared__ int sh[256];
    const int b = blockIdx.x, t = threadIdx.x;
    const int i = b * 256 + t;
    const int v = (i < N_NODES) ? g_deg[i] : 0;
    sh[t] = v;
    __syncthreads();
#pragma unroll
    for (int off = 1; off < 256; off <<= 1) {
        int u = (t >= off) ? sh[t - off] : 0;
        __syncthreads();
        sh[t] += u;
        __syncthreads();
    }
    const int excl = g_boff[b] + sh[t] - v;
    if (i < N_NODES) {
        g_rowstart[i] = excl;
        g_cursor[i]   = excl;
        if (i == N_NODES - 1) g_rowstart[N_NODES] = excl + v;
    }
}

__global__ void k_scatter() {
    int i = blockIdx.x * blockDim.x + threadIdx.x;
    if (i >= E_TOT) return;
    int s, d;
    if (i < E_EDGES) { s = g_src[i]; d = g_dst[i]; }
    else             { s = d = i - E_EDGES; }
    int pos = atomicAdd(&g_cursor[d], 1);
    g_csr[pos] = s;
}

// ---------------- GEMM1 + fused attention dots ----------------
#define BM 128
#define BN 128
#define BK 16
#define APAD 132
__global__ __launch_bounds__(256, 2) void k_gemm1(const float* __restrict__ x,
                                                  const float* __restrict__ W,
                                                  const float* __restrict__ atts,
                                                  const float* __restrict__ attd) {
    __shared__ __align__(16) float As[2][BK][APAD];
    __shared__ __align__(16) float Bs[2][BK][BN];
    const int bm = blockIdx.y * BM, bn = blockIdx.x * BN;
    const int t = threadIdx.x;
    const int tx = t & 15, ty = t >> 4;
    const int arow0 = t >> 2;
    const int akv   = (t & 3) * 4;
    const int brow0 = t >> 5;
    const int bcv   = (t & 31) * 4;

    unsigned long long acc[8][4];
#pragma unroll
    for (int i = 0; i < 8; i++)
#pragma unroll
        for (int j = 0; j < 4; j++) acc[i][j] = 0ULL;

    float4 pa[2], pb[2];
#pragma unroll
    for (int r = 0; r < 2; r++) {
        int row = arow0 + 64 * r;
        int gr = bm + row;
        pa[r] = make_float4(0.f, 0.f, 0.f, 0.f);
        if (gr < N_NODES) pa[r] = *(const float4*)&x[(size_t)gr * IN_DIM + akv];
        pb[r] = *(const float4*)&W[(size_t)(brow0 + 8 * r) * F1 + bn + bcv];
    }
#pragma unroll
    for (int r = 0; r < 2; r++) {
        int row = arow0 + 64 * r;
        As[0][akv + 0][row] = pa[r].x;
        As[0][akv + 1][row] = pa[r].y;
        As[0][akv + 2][row] = pa[r].z;
        As[0][akv + 3][row] = pa[r].w;
        *(float4*)&Bs[0][brow0 + 8 * r][bcv] = pb[r];
    }
    __syncthreads();

    int buf = 0;
    for (int k0 = 0; k0 < IN_DIM; k0 += BK) {
        const bool has_next = (k0 + BK) < IN_DIM;
        if (has_next) {
#pragma unroll
            for (int r = 0; r < 2; r++) {
                int row = arow0 + 64 * r;
                int gr = bm + row;
                pa[r] = make_float4(0.f, 0.f, 0.f, 0.f);
                if (gr < N_NODES)
                    pa[r] = *(const float4*)&x[(size_t)gr * IN_DIM + k0 + BK + akv];
                pb[r] = *(const float4*)&W[(size_t)(k0 + BK + brow0 + 8 * r) * F1 + bn + bcv];
            }
        }
#pragma unroll
        for (int kk = 0; kk < BK; kk++) {
            ulonglong2 bv0 = *(const ulonglong2*)&Bs[buf][kk][tx * 8];
            ulonglong2 bv1 = *(const ulonglong2*)&Bs[buf][kk][tx * 8 + 4];
            float4 a0 = *(const float4*)&As[buf][kk][ty * 8];
            float4 a1 = *(const float4*)&As[buf][kk][ty * 8 + 4];
            float a[8] = {a0.x, a0.y, a0.z, a0.w, a1.x, a1.y, a1.z, a1.w};
#pragma unroll
            for (int i = 0; i < 8; i++) {
                unsigned long long aa = pk2(a[i], a[i]);
                fma2(acc[i][0], aa, bv0.x);
                fma2(acc[i][1], aa, bv0.y);
                fma2(acc[i][2], aa, bv1.x);
                fma2(acc[i][3], aa, bv1.y);
            }
        }
        if (has_next) {
#pragma unroll
            for (int r = 0; r < 2; r++) {
                int row = arow0 + 64 * r;
                As[buf ^ 1][akv + 0][row] = pa[r].x;
                As[buf ^ 1][akv + 1][row] = pa[r].y;
                As[buf ^ 1][akv + 2][row] = pa[r].z;
                As[buf ^ 1][akv + 3][row] = pa[r].w;
                *(float4*)&Bs[buf ^ 1][brow0 + 8 * r][bcv] = pb[r];
            }
            __syncthreads();
            buf ^= 1;
        }
    }

    // epilogue: store h1 + fused attention partial dots
    const int col0 = bn + tx * 8;
    const int head = col0 >> 6;           // 64 channels per head
    float avS[8], avD[8];
#pragma unroll
    for (int j = 0; j < 8; j++) { avS[j] = atts[col0 + j]; avD[j] = attd[col0 + j]; }

#pragma unroll
    for (int i = 0; i < 8; i++) {
        int gr = bm + ty * 8 + i;
        float2 c0 = upk2(acc[i][0]), c1 = upk2(acc[i][1]);
        float2 c2 = upk2(acc[i][2]), c3 = upk2(acc[i][3]);
        float cv[8] = {c0.x, c0.y, c1.x, c1.y, c2.x, c2.y, c3.x, c3.y};
        if (gr < N_NODES) {
            *(float4*)&g_h1[(size_t)gr * F1 + col0]     = make_float4(cv[0], cv[1], cv[2], cv[3]);
            *(float4*)&g_h1[(size_t)gr * F1 + col0 + 4] = make_float4(cv[4], cv[5], cv[6], cv[7]);
        }
        float ps = 0.f, pd = 0.f;
#pragma unroll
        for (int j = 0; j < 8; j++) {
            ps = fmaf(cv[j], avS[j], ps);
            pd = fmaf(cv[j], avD[j], pd);
        }
#pragma unroll
        for (int off = 4; off; off >>= 1) {
            ps += __shfl_down_sync(0xffffffffu, ps, off, 8);
            pd += __shfl_down_sync(0xffffffffu, pd, off, 8);
        }
        if ((t & 7) == 0 && gr < N_NODES) {
            atomicAdd(&g_as1[gr * 4 + head], ps);
            atomicAdd(&g_ad1[gr * 4 + head], pd);
        }
    }
}

// ---------------- layer-1 aggregation: single-pass smem softmax + float4 gather ----
__global__ __launch_bounds__(256) void k_agg1(const float* __restrict__ b1) {
    const int dst = blockIdx.x;
    const int t = threadIdx.x;
    const int start = g_rowstart[dst];
    const int cnt = g_rowstart[dst + 1] - start;
    __shared__ __align__(16) float sal[MAXDEG][NH1];
    __shared__ __align__(16) float sacc[4][F1];
    __shared__ __align__(16) int   ssrc[MAXDEG];
    __shared__ float smax[NH1], ssum[NH1];
    float adv[NH1];
    {
        float4 a = *(const float4*)&g_ad1[dst * 4];
        adv[0] = a.x; adv[1] = a.y; adv[2] = a.z; adv[3] = a.w;
    }
    if (t < NH1) { smax[t] = NINF; ssum[t] = 0.f; }
    __syncthreads();

    if (cnt <= MAXDEG) {
        // ---- fast path: logits once into smem ----
        float lm[NH1] = {NINF, NINF, NINF, NINF};
        for (int i = t; i < cnt; i += 256) {
            int s = g_csr[start + i];
            ssrc[i] = s;
            float4 av = *(const float4*)&g_as1[s * 4];
            float e0 = lrelu(av.x + adv[0]);
            float e1 = lrelu(av.y + adv[1]);
            float e2 = lrelu(av.z + adv[2]);
            float e3 = lrelu(av.w + adv[3]);
            sal[i][0] = e0; sal[i][1] = e1; sal[i][2] = e2; sal[i][3] = e3;
            lm[0] = fmaxf(lm[0], e0); lm[1] = fmaxf(lm[1], e1);
            lm[2] = fmaxf(lm[2], e2); lm[3] = fmaxf(lm[3], e3);
        }
#pragma unroll
        for (int h = 0; h < NH1; h++) atomicMaxFloatS(&smax[h], lm[h]);
        __syncthreads();
        float mx[NH1];
#pragma unroll
        for (int h = 0; h < NH1; h++) mx[h] = smax[h];
        float ls[NH1] = {0.f, 0.f, 0.f, 0.f};
        for (int i = t; i < cnt; i += 256) {
#pragma unroll
            for (int h = 0; h < NH1; h++) {
                float ex = expf(sal[i][h] - mx[h]);
                sal[i][h] = ex;
                ls[h] += ex;
            }
        }
#pragma unroll
        for (int h = 0; h < NH1; h++) atomicAdd(&ssum[h], ls[h]);
        __syncthreads();

        // ---- gather: 4 edge-groups x 64 threads, float4 ----
        const int g = t >> 6, c = t & 63;
        const int hh = c >> 4;
        const float invh = 1.f / (ssum[hh] + 1e-16f);
        float4 a4 = make_float4(0.f, 0.f, 0.f, 0.f);
        for (int k = g; k < cnt; k += 4) {
            float a = sal[k][hh] * invh;
            float4 v = *(const float4*)&g_h1[(size_t)ssrc[k] * F1 + c * 4];
            a4.x = fmaf(a, v.x, a4.x);
            a4.y = fmaf(a, v.y, a4.y);
            a4.z = fmaf(a, v.z, a4.z);
            a4.w = fmaf(a, v.w, a4.w);
        }
        *(float4*)&sacc[g][c * 4] = a4;
        __syncthreads();
        float val = sacc[0][t] + sacc[1][t] + sacc[2][t] + sacc[3][t] + b1[t];
        g_hmid[(size_t)dst * F1 + t] = val > 0.f ? val : expm1f(val);
    } else {
        // ---- slow path (degree > MAXDEG): 3-pass gmem ----
        float lm[NH1] = {NINF, NINF, NINF, NINF};
        for (int i = t; i < cnt; i += 256) {
            int s = g_csr[start + i];
            float4 av = *(const float4*)&g_as1[s * 4];
            lm[0] = fmaxf(lm[0], lrelu(av.x + adv[0]));
            lm[1] = fmaxf(lm[1], lrelu(av.y + adv[1]));
            lm[2] = fmaxf(lm[2], lrelu(av.z + adv[2]));
            lm[3] = fmaxf(lm[3], lrelu(av.w + adv[3]));
        }
#pragma unroll
        for (int h = 0; h < NH1; h++) atomicMaxFloatS(&smax[h], lm[h]);
        __syncthreads();
        float mx[NH1];
#pragma unroll
        for (int h = 0; h < NH1; h++) mx[h] = smax[h];
        float ls[NH1] = {0.f, 0.f, 0.f, 0.f};
        for (int i = t; i < cnt; i += 256) {
            int s = g_csr[start + i];
            float4 av = *(const float4*)&g_as1[s * 4];
            ls[0] += expf(lrelu(av.x + adv[0]) - mx[0]);
            ls[1] += expf(lrelu(av.y + adv[1]) - mx[1]);
            ls[2] += expf(lrelu(av.z + adv[2]) - mx[2]);
            ls[3] += expf(lrelu(av.w + adv[3]) - mx[3]);
        }
#pragma unroll
        for (int h = 0; h < NH1; h++) atomicAdd(&ssum[h], ls[h]);
        __syncthreads();
        float inv[NH1];
#pragma unroll
        for (int h = 0; h < NH1; h++) inv[h] = 1.f / (ssum[h] + 1e-16f);

        const int g = t >> 6, c = t & 63;
        const int hh = c >> 4;
        float4 a4 = make_float4(0.f, 0.f, 0.f, 0.f);
        for (int base = 0; base < cnt; base += MAXDEG) {
            int n = min(MAXDEG, cnt - base);
            __syncthreads();
            for (int i = t; i < n; i += 256) {
                int s = g_csr[start + base + i];
                ssrc[i] = s;
                float4 av = *(const float4*)&g_as1[s * 4];
#pragma unroll
                for (int h = 0; h < NH1; h++)
                    sal[i][h] = expf(lrelu(((const float*)&av)[h] + adv[h]) - mx[h]) * inv[h];
            }
            __syncthreads();
            for (int k = g; k < n; k += 4) {
                float a = sal[k][hh];
                float4 v = *(const float4*)&g_h1[(size_t)ssrc[k] * F1 + c * 4];
                a4.x = fmaf(a, v.x, a4.x);
                a4.y = fmaf(a, v.y, a4.y);
                a4.z = fmaf(a, v.z, a4.z);
                a4.w = fmaf(a, v.w, a4.w);
            }
        }
        *(float4*)&sacc[g][c * 4] = a4;
        __syncthreads();
        float val = sacc[0][t] + sacc[1][t] + sacc[2][t] + sacc[3][t] + b1[t];
        g_hmid[(size_t)dst * F1 + t] = val > 0.f ? val : expm1f(val);
    }
}

// ---------------- GEMM2 + fused attention dots (no atomics) ----------------
#define BM2 128
#define BK2 32
__global__ __launch_bounds__(256) void k_gemm2(const float* __restrict__ W2,
                                               const float* __restrict__ atts,
                                               const float* __restrict__ attd) {
    __shared__ __align__(16) float As2[BM2][BK2 + 4];
    __shared__ __align__(16) float Ws[BK2][F2];
    const int bm = blockIdx.x * BM2;
    const int t = threadIdx.x;
    const int tx = t & 7;
    const int ty = t >> 3;
    float acc[4][5];
#pragma unroll
    for (int i = 0; i < 4; i++)
#pragma unroll
        for (int j = 0; j < 5; j++) acc[i][j] = 0.f;

    for (int k0 = 0; k0 < F1; k0 += BK2) {
#pragma unroll
        for (int r = 0; r < 4; r++) {
            int f = t + r * 256;
            int row = f >> 3;
            int cv = (f & 7) * 4;
            float4 v = make_float4(0.f, 0.f, 0.f, 0.f);
            int gr = bm + row;
            if (gr < N_NODES) v = *(const float4*)&g_hmid[(size_t)gr * F1 + k0 + cv];
            *(float4*)&As2[row][cv] = v;
        }
        for (int idx = t; idx < BK2 * F2; idx += 256) {
            int r = idx / F2, c = idx % F2;
            Ws[r][c] = W2[(size_t)(k0 + r) * F2 + c];
        }
        __syncthreads();
#pragma unroll
        for (int kk = 0; kk < BK2; kk++) {
            float a[4], b[5];
#pragma unroll
            for (int i = 0; i < 4; i++) a[i] = As2[ty * 4 + i][kk];
#pragma unroll
            for (int j = 0; j < 5; j++) b[j] = Ws[kk][tx * 5 + j];
#pragma unroll
            for (int i = 0; i < 4; i++)
#pragma unroll
                for (int j = 0; j < 5; j++) acc[i][j] = fmaf(a[i], b[j], acc[i][j]);
        }
        __syncthreads();
    }

    float avS[5], avD[5];
#pragma unroll
    for (int j = 0; j < 5; j++) { avS[j] = atts[tx * 5 + j]; avD[j] = attd[tx * 5 + j]; }
#pragma unroll
    for (int i = 0; i < 4; i++) {
        int gr = bm + ty * 4 + i;
        if (gr < N_NODES)
#pragma unroll
            for (int j = 0; j < 5; j++)
                g_h2[(size_t)gr * F2 + tx * 5 + j] = acc[i][j];
        float ps = 0.f, pd = 0.f;
#pragma unroll
        for (int j = 0; j < 5; j++) {
            ps = fmaf(acc[i][j], avS[j], ps);
            pd = fmaf(acc[i][j], avD[j], pd);
        }
#pragma unroll
        for (int off = 4; off; off >>= 1) {
            ps += __shfl_down_sync(0xffffffffu, ps, off, 8);
            pd += __shfl_down_sync(0xffffffffu, pd, off, 8);
        }
        if (tx == 0 && gr < N_NODES) { g_as2[gr] = ps; g_ad2[gr] = pd; }
    }
}

// ---------------- layer-2 aggregation + bias + log_softmax ----------------
__global__ __launch_bounds__(128) void k_agg2(const float* __restrict__ b2,
                                              float* __restrict__ out) {
    const int dst = blockIdx.x;
    const int t = threadIdx.x;
    const int start = g_rowstart[dst];
    const int cnt = g_rowstart[dst + 1] - start;
    __shared__ __align__(16) float sal[MAXDEG];
    __shared__ __align__(16) float sacc[4][F2];
    __shared__ __align__(16) float sv[F2];
    __shared__ __align__(16) int   ssrc[MAXDEG];
    __shared__ float smax, ssum, slog;
    const float adv = g_ad2[dst];
    if (t == 0) { smax = NINF; ssum = 0.f; }
    __syncthreads();

    const int g = t >> 5, c = t & 31;   // 4 edge-groups of 32 lanes

    if (cnt <= MAXDEG) {
        float lm = NINF;
        for (int i = t; i < cnt; i += 128) {
            int s = g_csr[start + i];
            ssrc[i] = s;
            float e = lrelu(g_as2[s] + adv);
            sal[i] = e;
            lm = fmaxf(lm, e);
        }
        atomicMaxFloatS(&smax, lm);
        __syncthreads();
        const float mx = smax;
        float ls = 0.f;
        for (int i = t; i < cnt; i += 128) {
            float ex = expf(sal[i] - mx);
            sal[i] = ex;
            ls += ex;
        }
        atomicAdd(&ssum, ls);
        __syncthreads();
        const float inv = 1.f / (ssum + 1e-16f);

        float4 a4 = make_float4(0.f, 0.f, 0.f, 0.f);
        if (c < 10) {
            for (int k = g; k < cnt; k += 4) {
                float a = sal[k] * inv;
                float4 v = *(const float4*)&g_h2[(size_t)ssrc[k] * F2 + c * 4];
                a4.x = fmaf(a, v.x, a4.x);
                a4.y = fmaf(a, v.y, a4.y);
                a4.z = fmaf(a, v.z, a4.z);
                a4.w = fmaf(a, v.w, a4.w);
            }
            *(float4*)&sacc[g][c * 4] = a4;
        }
        __syncthreads();
    } else {
        float lm = NINF;
        for (int i = t; i < cnt; i += 128)
            lm = fmaxf(lm, lrelu(g_as2[g_csr[start + i]] + adv));
        atomicMaxFloatS(&smax, lm);
        __syncthreads();
        const float mx = smax;
        float ls = 0.f;
        for (int i = t; i < cnt; i += 128)
            ls += expf(lrelu(g_as2[g_csr[start + i]] + adv) - mx);
        atomicAdd(&ssum, ls);
        __syncthreads();
        const float inv = 1.f / (ssum + 1e-16f);

        float4 a4 = make_float4(0.f, 0.f, 0.f, 0.f);
        for (int base = 0; base < cnt; base += MAXDEG) {
            int n = min(MAXDEG, cnt - base);
            __syncthreads();
            for (int i = t; i < n; i += 128) {
                int s = g_csr[start + base + i];
                ssrc[i] = s;
                sal[i] = expf(lrelu(g_as2[s] + adv) - mx) * inv;
            }
            __syncthreads();
            if (c < 10) {
                for (int k = g; k < n; k += 4) {
                    float a = sal[k];
                    float4 v = *(const float4*)&g_h2[(size_t)ssrc[k] * F2 + c * 4];
                    a4.x = fmaf(a, v.x, a4.x);
                    a4.y = fmaf(a, v.y, a4.y);
                    a4.z = fmaf(a, v.z, a4.z);
                    a4.w = fmaf(a, v.w, a4.w);
                }
            }
        }
        if (c < 10) *(float4*)&sacc[g][c * 4] = a4;
        __syncthreads();
    }

    if (t < F2)
        sv[t] = sacc[0][t] + sacc[1][t] + sacc[2][t] + sacc[3][t] + b2[t];
    __syncthreads();
    if (t == 0) {
        float m2 = NINF;
        for (int i = 0; i < F2; i++) m2 = fmaxf(m2, sv[i]);
        float se = 0.f;
        for (int i = 0; i < F2; i++) se += expf(sv[i] - m2);
        smax = m2;
        slog = logf(se);
    }
    __syncthreads();
    if (t < F2) out[(size_t)dst * F2 + t] = sv[t] - smax - slog;
}

// ---------------- launch ----------------
extern "C" void kernel_launch(void* const* d_in, const int* in_sizes, int n_in,
                              void* d_out, int out_size) {
    const float* x   = (const float*)d_in[0];
    const void*  ei  = d_in[1];
    const float* W1  = (const float*)d_in[2];
    const float* as1 = (const float*)d_in[3];
    const float* ad1 = (const float*)d_in[4];
    const float* b1  = (const float*)d_in[5];
    const float* W2  = (const float*)d_in[6];
    const float* as2 = (const float*)d_in[7];
    const float* ad2 = (const float*)d_in[8];
    const float* b2  = (const float*)d_in[9];
    float* out = (float*)d_out;

    k_init<<<SCAN_BLOCKS, 256>>>((const int*)ei);            // #1
    k_convert_count<<<(E_EDGES + 255) / 256, 256>>>(ei);     // #2
    k_bsum<<<SCAN_BLOCKS, 256>>>();                          // #3
    dim3 g1(F1 / BN, (N_NODES + BM - 1) / BM);
    k_gemm1<<<g1, 256>>>(x, W1, as1, ad1);                   // #4  <- profiled
    k_bscan<<<1, 256>>>();                                   // #5
    k_rowstart<<<SCAN_BLOCKS, 256>>>();                      // #6
    k_scatter<<<(E_TOT + 255) / 256, 256>>>();               // #7
    k_agg1<<<N_NODES, 256>>>(b1);                            // #8
    k_gemm2<<<(N_NODES + BM2 - 1) / BM2, 256>>>(W2, as2, ad2);
    k_agg2<<<N_NODES, 128>>>(b2, out);
}

// round 8
// speedup vs baseline: 2.4905x; 2.2939x over previous
#include <cuda_runtime.h>
#include <math.h>

#define N_NODES 50000
#define E_EDGES 800000
#define E_TOT   (E_EDGES + N_NODES)
#define IN_DIM  512
#define F1      256
#define NH1     4
#define F2      40
#define NEG_SLOPE 0.2f
#define NINF (-__int_as_float(0x7f800000))
#define SCAN_BLOCKS 196   // 196*256 = 50176 >= N_NODES

// ---------------- scratch (static device allocations only) ----------------
__device__ int   g_is64;
__device__ int   g_src[E_EDGES];
__device__ int   g_dst[E_EDGES];
__device__ int   g_deg[N_NODES];
__device__ int   g_bsum[SCAN_BLOCKS];
__device__ int   g_rowstart[N_NODES + 1];
__device__ int   g_cursor[N_NODES];
__device__ int   g_csr[E_TOT];
__device__ __align__(16) float g_h1[(size_t)N_NODES * F1];
__device__ __align__(16) float g_as1[N_NODES * NH1];
__device__ __align__(16) float g_ad1[N_NODES * NH1];
__device__ __align__(16) float g_hmid[(size_t)N_NODES * F1];
__device__ __align__(16) float g_h2[(size_t)N_NODES * F2];
__device__ float g_as2[N_NODES];
__device__ float g_ad2[N_NODES];

// ---------------- helpers ----------------
__device__ __forceinline__ float lrelu(float x) { return x > 0.f ? x : NEG_SLOPE * x; }

__device__ __forceinline__ unsigned long long pk2(float lo, float hi) {
    unsigned long long r;
    asm("mov.b64 %0, {%1, %2};" : "=l"(r) : "f"(lo), "f"(hi));
    return r;
}
__device__ __forceinline__ void fma2(unsigned long long& d, unsigned long long a,
                                     unsigned long long b) {
    asm("fma.rn.f32x2 %0, %1, %2, %0;" : "+l"(d) : "l"(a), "l"(b));
}
__device__ __forceinline__ float2 upk2(unsigned long long v) {
    float2 r;
    asm("mov.b64 {%0, %1}, %2;" : "=f"(r.x), "=f"(r.y) : "l"(v));
    return r;
}

// ---------------- init: self-loop degree, zero attn accumulators, dtype detect ----
__global__ void k_init(const int* e32) {
    int i = blockIdx.x * blockDim.x + threadIdx.x;
    if (i < N_NODES) {
        g_deg[i] = 1;  // self loop
        *(float4*)&g_as1[i * 4] = make_float4(0.f, 0.f, 0.f, 0.f);
        *(float4*)&g_ad1[i * 4] = make_float4(0.f, 0.f, 0.f, 0.f);
    }
    if (i == 0) {
        int allzero = 1;
        for (int j = 1; j < 256; j += 2) if (e32[j] != 0) allzero = 0;
        g_is64 = allzero;
    }
}

__global__ void k_convert_count(const void* eptr) {
    int i = blockIdx.x * blockDim.x + threadIdx.x;
    if (i >= E_EDGES) return;
    int s, d;
    if (g_is64) {
        const long long* e = (const long long*)eptr;
        s = (int)e[i];
        d = (int)e[E_EDGES + i];
    } else {
        const int* e = (const int*)eptr;
        s = e[i];
        d = e[E_EDGES + i];
    }
    g_src[i] = s;
    g_dst[i] = d;
    atomicAdd(&g_deg[d], 1);
}

// ---------------- CSR scan (2 kernels) ----------------
__global__ void k_bsum() {
    __shared__ int sh[256];
    const int b = blockIdx.x, t = threadIdx.x;
    const int i = b * 256 + t;
    sh[t] = (i < N_NODES) ? g_deg[i] : 0;
    __syncthreads();
#pragma unroll
    for (int off = 128; off; off >>= 1) {
        if (t < off) sh[t] += sh[t + off];
        __syncthreads();
    }
    if (t == 0) g_bsum[b] = sh[0];
}

// per-block prefix of bsum computed locally; then local scan writes rowstart
__global__ void k_rowstart2() {
    __shared__ int sred[256];
    __shared__ int sh[256];
    const int b = blockIdx.x, t = threadIdx.x;
    sred[t] = (t < b) ? g_bsum[t] : 0;   // b <= 195 < 256
    __syncthreads();
#pragma unroll
    for (int off = 128; off; off >>= 1) {
        if (t < off) sred[t] += sred[t + off];
        __syncthreads();
    }
    const int boff = sred[0];

    const int i = b * 256 + t;
    const int v = (i < N_NODES) ? g_deg[i] : 0;
    sh[t] = v;
    __syncthreads();
#pragma unroll
    for (int off = 1; off < 256; off <<= 1) {
        int u = (t >= off) ? sh[t - off] : 0;
        __syncthreads();
        sh[t] += u;
        __syncthreads();
    }
    const int excl = boff + sh[t] - v;
    if (i < N_NODES) {
        g_rowstart[i] = excl;
        g_cursor[i]   = excl;
        if (i == N_NODES - 1) g_rowstart[N_NODES] = excl + v;
    }
}

__global__ void k_scatter() {
    int i = blockIdx.x * blockDim.x + threadIdx.x;
    if (i >= E_TOT) return;
    int s, d;
    if (i < E_EDGES) { s = g_src[i]; d = g_dst[i]; }
    else             { s = d = i - E_EDGES; }
    int pos = atomicAdd(&g_cursor[d], 1);
    g_csr[pos] = s;
}

// ---------------- GEMM1 + fused attention dots ----------------
#define BM 128
#define BN 128
#define BK 16
#define APAD 132
__global__ __launch_bounds__(256, 2) void k_gemm1(const float* __restrict__ x,
                                                  const float* __restrict__ W,
                                                  const float* __restrict__ atts,
                                                  const float* __restrict__ attd) {
    __shared__ __align__(16) float As[2][BK][APAD];
    __shared__ __align__(16) float Bs[2][BK][BN];
    const int bm = blockIdx.y * BM, bn = blockIdx.x * BN;
    const int t = threadIdx.x;
    const int tx = t & 15, ty = t >> 4;
    const int arow0 = t >> 2;
    const int akv   = (t & 3) * 4;
    const int brow0 = t >> 5;
    const int bcv   = (t & 31) * 4;

    unsigned long long acc[8][4];
#pragma unroll
    for (int i = 0; i < 8; i++)
#pragma unroll
        for (int j = 0; j < 4; j++) acc[i][j] = 0ULL;

    float4 pa[2], pb[2];
#pragma unroll
    for (int r = 0; r < 2; r++) {
        int row = arow0 + 64 * r;
        int gr = bm + row;
        pa[r] = make_float4(0.f, 0.f, 0.f, 0.f);
        if (gr < N_NODES) pa[r] = *(const float4*)&x[(size_t)gr * IN_DIM + akv];
        pb[r] = *(const float4*)&W[(size_t)(brow0 + 8 * r) * F1 + bn + bcv];
    }
#pragma unroll
    for (int r = 0; r < 2; r++) {
        int row = arow0 + 64 * r;
        As[0][akv + 0][row] = pa[r].x;
        As[0][akv + 1][row] = pa[r].y;
        As[0][akv + 2][row] = pa[r].z;
        As[0][akv + 3][row] = pa[r].w;
        *(float4*)&Bs[0][brow0 + 8 * r][bcv] = pb[r];
    }
    __syncthreads();

    int buf = 0;
    for (int k0 = 0; k0 < IN_DIM; k0 += BK) {
        const bool has_next = (k0 + BK) < IN_DIM;
        if (has_next) {
#pragma unroll
            for (int r = 0; r < 2; r++) {
                int row = arow0 + 64 * r;
                int gr = bm + row;
                pa[r] = make_float4(0.f, 0.f, 0.f, 0.f);
                if (gr < N_NODES)
                    pa[r] = *(const float4*)&x[(size_t)gr * IN_DIM + k0 + BK + akv];
                pb[r] = *(const float4*)&W[(size_t)(k0 + BK + brow0 + 8 * r) * F1 + bn + bcv];
            }
        }
#pragma unroll
        for (int kk = 0; kk < BK; kk++) {
            ulonglong2 bv0 = *(const ulonglong2*)&Bs[buf][kk][tx * 8];
            ulonglong2 bv1 = *(const ulonglong2*)&Bs[buf][kk][tx * 8 + 4];
            float4 a0 = *(const float4*)&As[buf][kk][ty * 8];
            float4 a1 = *(const float4*)&As[buf][kk][ty * 8 + 4];
            float a[8] = {a0.x, a0.y, a0.z, a0.w, a1.x, a1.y, a1.z, a1.w};
#pragma unroll
            for (int i = 0; i < 8; i++) {
                unsigned long long aa = pk2(a[i], a[i]);
                fma2(acc[i][0], aa, bv0.x);
                fma2(acc[i][1], aa, bv0.y);
                fma2(acc[i][2], aa, bv1.x);
                fma2(acc[i][3], aa, bv1.y);
            }
        }
        if (has_next) {
#pragma unroll
            for (int r = 0; r < 2; r++) {
                int row = arow0 + 64 * r;
                As[buf ^ 1][akv + 0][row] = pa[r].x;
                As[buf ^ 1][akv + 1][row] = pa[r].y;
                As[buf ^ 1][akv + 2][row] = pa[r].z;
                As[buf ^ 1][akv + 3][row] = pa[r].w;
                *(float4*)&Bs[buf ^ 1][brow0 + 8 * r][bcv] = pb[r];
            }
            __syncthreads();
            buf ^= 1;
        }
    }

    const int col0 = bn + tx * 8;
    const int head = col0 >> 6;
    float avS[8], avD[8];
#pragma unroll
    for (int j = 0; j < 8; j++) { avS[j] = atts[col0 + j]; avD[j] = attd[col0 + j]; }

#pragma unroll
    for (int i = 0; i < 8; i++) {
        int gr = bm + ty * 8 + i;
        float2 c0 = upk2(acc[i][0]), c1 = upk2(acc[i][1]);
        float2 c2 = upk2(acc[i][2]), c3 = upk2(acc[i][3]);
        float cv[8] = {c0.x, c0.y, c1.x, c1.y, c2.x, c2.y, c3.x, c3.y};
        if (gr < N_NODES) {
            *(float4*)&g_h1[(size_t)gr * F1 + col0]     = make_float4(cv[0], cv[1], cv[2], cv[3]);
            *(float4*)&g_h1[(size_t)gr * F1 + col0 + 4] = make_float4(cv[4], cv[5], cv[6], cv[7]);
        }
        float ps = 0.f, pd = 0.f;
#pragma unroll
        for (int j = 0; j < 8; j++) {
            ps = fmaf(cv[j], avS[j], ps);
            pd = fmaf(cv[j], avD[j], pd);
        }
#pragma unroll
        for (int off = 4; off; off >>= 1) {
            ps += __shfl_down_sync(0xffffffffu, ps, off, 8);
            pd += __shfl_down_sync(0xffffffffu, pd, off, 8);
        }
        if ((t & 7) == 0 && gr < N_NODES) {
            atomicAdd(&g_as1[gr * 4 + head], ps);
            atomicAdd(&g_ad1[gr * 4 + head], pd);
        }
    }
}

// ---------------- layer-1 aggregation: WARP per node ----------------
// No smem, no __syncthreads, no smem atomics. Lane owns 8 channels.
__global__ __launch_bounds__(256) void k_agg1w(const float* __restrict__ b1) {
    const int node = blockIdx.x * 8 + (threadIdx.x >> 5);  // 6250*8 = 50000 exact
    const int lane = threadIdx.x & 31;
    const int start = g_rowstart[node];
    const int cnt = g_rowstart[node + 1] - start;

    float4 adv = *(const float4*)&g_ad1[node * 4];

    // phase 1: per-head max (lane-per-edge, shfl reduce)
    float m0 = NINF, m1 = NINF, m2 = NINF, m3 = NINF;
    for (int e = lane; e < cnt; e += 32) {
        int s = g_csr[start + e];
        float4 av = *(const float4*)&g_as1[s * 4];
        m0 = fmaxf(m0, lrelu(av.x + adv.x));
        m1 = fmaxf(m1, lrelu(av.y + adv.y));
        m2 = fmaxf(m2, lrelu(av.z + adv.z));
        m3 = fmaxf(m3, lrelu(av.w + adv.w));
    }
#pragma unroll
    for (int off = 16; off; off >>= 1) {
        m0 = fmaxf(m0, __shfl_xor_sync(0xffffffffu, m0, off));
        m1 = fmaxf(m1, __shfl_xor_sync(0xffffffffu, m1, off));
        m2 = fmaxf(m2, __shfl_xor_sync(0xffffffffu, m2, off));
        m3 = fmaxf(m3, __shfl_xor_sync(0xffffffffu, m3, off));
    }

    // phase 2: per-head sum of exp
    float s0 = 0.f, s1 = 0.f, s2 = 0.f, s3 = 0.f;
    for (int e = lane; e < cnt; e += 32) {
        int s = g_csr[start + e];
        float4 av = *(const float4*)&g_as1[s * 4];
        s0 += expf(lrelu(av.x + adv.x) - m0);
        s1 += expf(lrelu(av.y + adv.y) - m1);
        s2 += expf(lrelu(av.z + adv.z) - m2);
        s3 += expf(lrelu(av.w + adv.w) - m3);
    }
#pragma unroll
    for (int off = 16; off; off >>= 1) {
        s0 += __shfl_xor_sync(0xffffffffu, s0, off);
        s1 += __shfl_xor_sync(0xffffffffu, s1, off);
        s2 += __shfl_xor_sync(0xffffffffu, s2, off);
        s3 += __shfl_xor_sync(0xffffffffu, s3, off);
    }

    // lane-specific head params (lane owns channels [lane*8, lane*8+8), head = lane>>3)
    const int hh = lane >> 3;
    float advh = (hh == 0) ? adv.x : (hh == 1) ? adv.y : (hh == 2) ? adv.z : adv.w;
    float mh   = (hh == 0) ? m0    : (hh == 1) ? m1    : (hh == 2) ? m2    : m3;
    float sumh = (hh == 0) ? s0    : (hh == 1) ? s1    : (hh == 2) ? s2    : s3;
    const float invh = 1.f / (sumh + 1e-16f);

    // phase 3: gather (warp reads whole 1KB source row, coalesced)
    float4 a0 = make_float4(0.f, 0.f, 0.f, 0.f);
    float4 a1 = make_float4(0.f, 0.f, 0.f, 0.f);
    const int coff = lane * 8;
    for (int e = 0; e < cnt; e++) {
        int s = g_csr[start + e];                       // uniform broadcast load
        float av = __ldg(&g_as1[s * 4 + hh]);           // L1 hit
        float al = expf(lrelu(av + advh) - mh) * invh;
        const float* row = &g_h1[(size_t)s * F1 + coff];
        float4 v0 = *(const float4*)row;
        float4 v1 = *(const float4*)(row + 4);
        a0.x = fmaf(al, v0.x, a0.x); a0.y = fmaf(al, v0.y, a0.y);
        a0.z = fmaf(al, v0.z, a0.z); a0.w = fmaf(al, v0.w, a0.w);
        a1.x = fmaf(al, v1.x, a1.x); a1.y = fmaf(al, v1.y, a1.y);
        a1.z = fmaf(al, v1.z, a1.z); a1.w = fmaf(al, v1.w, a1.w);
    }

    float4 bb0 = *(const float4*)&b1[coff];
    float4 bb1 = *(const float4*)&b1[coff + 4];
    float r0 = a0.x + bb0.x, r1 = a0.y + bb0.y, r2 = a0.z + bb0.z, r3 = a0.w + bb0.w;
    float r4 = a1.x + bb1.x, r5 = a1.y + bb1.y, r6 = a1.z + bb1.z, r7 = a1.w + bb1.w;
    r0 = r0 > 0.f ? r0 : expm1f(r0); r1 = r1 > 0.f ? r1 : expm1f(r1);
    r2 = r2 > 0.f ? r2 : expm1f(r2); r3 = r3 > 0.f ? r3 : expm1f(r3);
    r4 = r4 > 0.f ? r4 : expm1f(r4); r5 = r5 > 0.f ? r5 : expm1f(r5);
    r6 = r6 > 0.f ? r6 : expm1f(r6); r7 = r7 > 0.f ? r7 : expm1f(r7);
    float* orow = &g_hmid[(size_t)node * F1 + coff];
    *(float4*)orow       = make_float4(r0, r1, r2, r3);
    *(float4*)(orow + 4) = make_float4(r4, r5, r6, r7);
}

// ---------------- GEMM2 + fused attention dots (transposed A, conflict-free) ----
#define BM2 128
#define BK2 32
#define A2PAD 132
__global__ __launch_bounds__(256) void k_gemm2(const float* __restrict__ W2,
                                               const float* __restrict__ atts,
                                               const float* __restrict__ attd) {
    __shared__ __align__(16) float As2t[BK2][A2PAD];   // transposed A tile
    __shared__ __align__(16) float Ws[BK2][F2];
    const int bm = blockIdx.x * BM2;
    const int t = threadIdx.x;
    const int tx = t & 7;
    const int ty = t >> 3;
    float acc[4][5];
#pragma unroll
    for (int i = 0; i < 4; i++)
#pragma unroll
        for (int j = 0; j < 5; j++) acc[i][j] = 0.f;

    for (int k0 = 0; k0 < F1; k0 += BK2) {
#pragma unroll
        for (int r = 0; r < 4; r++) {
            int f = t + r * 256;
            int row = f >> 3;
            int cv = (f & 7) * 4;
            float4 v = make_float4(0.f, 0.f, 0.f, 0.f);
            int gr = bm + row;
            if (gr < N_NODES) v = *(const float4*)&g_hmid[(size_t)gr * F1 + k0 + cv];
            As2t[cv + 0][row] = v.x;
            As2t[cv + 1][row] = v.y;
            As2t[cv + 2][row] = v.z;
            As2t[cv + 3][row] = v.w;
        }
        for (int idx = t; idx < BK2 * F2; idx += 256) {
            int r = idx / F2, c = idx % F2;
            Ws[r][c] = W2[(size_t)(k0 + r) * F2 + c];
        }
        __syncthreads();
#pragma unroll
        for (int kk = 0; kk < BK2; kk++) {
            float4 a4 = *(const float4*)&As2t[kk][ty * 4];
            float a[4] = {a4.x, a4.y, a4.z, a4.w};
            float b[5];
#pragma unroll
            for (int j = 0; j < 5; j++) b[j] = Ws[kk][tx * 5 + j];
#pragma unroll
            for (int i = 0; i < 4; i++)
#pragma unroll
                for (int j = 0; j < 5; j++) acc[i][j] = fmaf(a[i], b[j], acc[i][j]);
        }
        __syncthreads();
    }

    float avS[5], avD[5];
#pragma unroll
    for (int j = 0; j < 5; j++) { avS[j] = atts[tx * 5 + j]; avD[j] = attd[tx * 5 + j]; }
#pragma unroll
    for (int i = 0; i < 4; i++) {
        int gr = bm + ty * 4 + i;
        if (gr < N_NODES)
#pragma unroll
            for (int j = 0; j < 5; j++)
                g_h2[(size_t)gr * F2 + tx * 5 + j] = acc[i][j];
        float ps = 0.f, pd = 0.f;
#pragma unroll
        for (int j = 0; j < 5; j++) {
            ps = fmaf(acc[i][j], avS[j], ps);
            pd = fmaf(acc[i][j], avD[j], pd);
        }
#pragma unroll
        for (int off = 4; off; off >>= 1) {
            ps += __shfl_down_sync(0xffffffffu, ps, off, 8);
            pd += __shfl_down_sync(0xffffffffu, pd, off, 8);
        }
        if (tx == 0 && gr < N_NODES) { g_as2[gr] = ps; g_ad2[gr] = pd; }
    }
}

// ---------------- layer-2 aggregation + log_softmax: WARP per node ----------------
__global__ __launch_bounds__(256) void k_agg2w(const float* __restrict__ b2,
                                               float* __restrict__ out) {
    const int node = blockIdx.x * 8 + (threadIdx.x >> 5);
    const int lane = threadIdx.x & 31;
    const int start = g_rowstart[node];
    const int cnt = g_rowstart[node + 1] - start;
    const float adv = g_ad2[node];

    float m = NINF;
    for (int e = lane; e < cnt; e += 32)
        m = fmaxf(m, lrelu(g_as2[g_csr[start + e]] + adv));
#pragma unroll
    for (int off = 16; off; off >>= 1)
        m = fmaxf(m, __shfl_xor_sync(0xffffffffu, m, off));

    float se = 0.f;
    for (int e = lane; e < cnt; e += 32)
        se += expf(lrelu(g_as2[g_csr[start + e]] + adv) - m);
#pragma unroll
    for (int off = 16; off; off >>= 1)
        se += __shfl_xor_sync(0xffffffffu, se, off);
    const float inv = 1.f / (se + 1e-16f);

    // gather: lane owns channel lane (+ channel 32+lane for lane<8)
    float a0 = 0.f, a1 = 0.f;
    for (int e = 0; e < cnt; e++) {
        int s = g_csr[start + e];                    // uniform broadcast load
        float al = expf(lrelu(__ldg(&g_as2[s]) + adv) - m) * inv;
        const float* row = &g_h2[(size_t)s * F2];
        a0 = fmaf(al, row[lane], a0);
        if (lane < 8) a1 = fmaf(al, row[32 + lane], a1);
    }
    float v0 = a0 + b2[lane];
    float v1 = (lane < 8) ? (a1 + b2[32 + lane]) : NINF;

    // log_softmax across the 40 values held by the warp
    float mm = fmaxf(v0, v1);
#pragma unroll
    for (int off = 16; off; off >>= 1)
        mm = fmaxf(mm, __shfl_xor_sync(0xffffffffu, mm, off));
    float s2 = expf(v0 - mm) + ((lane < 8) ? expf(v1 - mm) : 0.f);
#pragma unroll
    for (int off = 16; off; off >>= 1)
        s2 += __shfl_xor_sync(0xffffffffu, s2, off);
    const float lg = logf(s2);

    float* orow = &out[(size_t)node * F2];
    orow[lane] = v0 - mm - lg;
    if (lane < 8) orow[32 + lane] = v1 - mm - lg;
}

// ---------------- launch ----------------
extern "C" void kernel_launch(void* const* d_in, const int* in_sizes, int n_in,
                              void* d_out, int out_size) {
    const float* x   = (const float*)d_in[0];
    const void*  ei  = d_in[1];
    const float* W1  = (const float*)d_in[2];
    const float* as1 = (const float*)d_in[3];
    const float* ad1 = (const float*)d_in[4];
    const float* b1  = (const float*)d_in[5];
    const float* W2  = (const float*)d_in[6];
    const float* as2 = (const float*)d_in[7];
    const float* ad2 = (const float*)d_in[8];
    const float* b2  = (const float*)d_in[9];
    float* out = (float*)d_out;

    k_init<<<SCAN_BLOCKS, 256>>>((const int*)ei);            // #1
    k_convert_count<<<(E_EDGES + 255) / 256, 256>>>(ei);     // #2
    k_bsum<<<SCAN_BLOCKS, 256>>>();                          // #3
    dim3 g1(F1 / BN, (N_NODES + BM - 1) / BM);
    k_gemm1<<<g1, 256>>>(x, W1, as1, ad1);                   // #4  <- profiled
    k_rowstart2<<<SCAN_BLOCKS, 256>>>();                     // #5
    k_scatter<<<(E_TOT + 255) / 256, 256>>>();               // #6
    k_agg1w<<<N_NODES / 8, 256>>>(b1);                       // #7
    k_gemm2<<<(N_NODES + BM2 - 1) / BM2, 256>>>(W2, as2, ad2);  // #8
    k_agg2w<<<N_NODES / 8, 256>>>(b2, out);                  // #9
}

// round 9
// speedup vs baseline: 2.5101x; 1.0079x over previous
#include <cuda_runtime.h>
#include <math.h>

#define N_NODES 50000
#define E_EDGES 800000
#define E_TOT   (E_EDGES + N_NODES)
#define IN_DIM  512
#define F1      256
#define NH1     4
#define F2      40
#define NEG_SLOPE 0.2f
#define NINF (-__int_as_float(0x7f800000))
#define SCAN_BLOCKS 196   // 196*256 = 50176 >= N_NODES

// ---------------- scratch (static device allocations only) ----------------
__device__ int   g_is64;
__device__ int   g_src[E_EDGES];
__device__ int   g_dst[E_EDGES];
__device__ int   g_deg[N_NODES];
__device__ int   g_bsum[SCAN_BLOCKS];
__device__ int   g_rowstart[N_NODES + 1];
__device__ int   g_cursor[N_NODES];
__device__ int   g_csr[E_TOT];
__device__ __align__(16) float g_h1[(size_t)N_NODES * F1];
__device__ __align__(16) float g_as1[N_NODES * NH1];
__device__ __align__(16) float g_ad1[N_NODES * NH1];
__device__ __align__(16) float g_hmid[(size_t)N_NODES * F1];
__device__ __align__(16) float g_h2[(size_t)N_NODES * F2];
__device__ float g_as2[N_NODES];
__device__ float g_ad2[N_NODES];

// ---------------- helpers ----------------
__device__ __forceinline__ float lrelu(float x) { return x > 0.f ? x : NEG_SLOPE * x; }

__device__ __forceinline__ unsigned long long pk2(float lo, float hi) {
    unsigned long long r;
    asm("mov.b64 %0, {%1, %2};" : "=l"(r) : "f"(lo), "f"(hi));
    return r;
}
__device__ __forceinline__ void fma2(unsigned long long& d, unsigned long long a,
                                     unsigned long long b) {
    asm("fma.rn.f32x2 %0, %1, %2, %0;" : "+l"(d) : "l"(a), "l"(b));
}
__device__ __forceinline__ float2 upk2(unsigned long long v) {
    float2 r;
    asm("mov.b64 {%0, %1}, %2;" : "=f"(r.x), "=f"(r.y) : "l"(v));
    return r;
}

// ---------------- init: self-loop degree, zero attn accumulators, dtype detect ----
__global__ void k_init(const int* e32) {
    int i = blockIdx.x * blockDim.x + threadIdx.x;
    if (i < N_NODES) {
        g_deg[i] = 1;  // self loop
        *(float4*)&g_as1[i * 4] = make_float4(0.f, 0.f, 0.f, 0.f);
        *(float4*)&g_ad1[i * 4] = make_float4(0.f, 0.f, 0.f, 0.f);
    }
    if (i == 0) {
        int allzero = 1;
        for (int j = 1; j < 256; j += 2) if (e32[j] != 0) allzero = 0;
        g_is64 = allzero;
    }
}

__global__ void k_convert_count(const void* eptr) {
    int i = blockIdx.x * blockDim.x + threadIdx.x;
    if (i >= E_EDGES) return;
    int s, d;
    if (g_is64) {
        const long long* e = (const long long*)eptr;
        s = (int)e[i];
        d = (int)e[E_EDGES + i];
    } else {
        const int* e = (const int*)eptr;
        s = e[i];
        d = e[E_EDGES + i];
    }
    g_src[i] = s;
    g_dst[i] = d;
    atomicAdd(&g_deg[d], 1);
}

// ---------------- CSR scan (2 kernels) ----------------
__global__ void k_bsum() {
    __shared__ int sh[256];
    const int b = blockIdx.x, t = threadIdx.x;
    const int i = b * 256 + t;
    sh[t] = (i < N_NODES) ? g_deg[i] : 0;
    __syncthreads();
#pragma unroll
    for (int off = 128; off; off >>= 1) {
        if (t < off) sh[t] += sh[t + off];
        __syncthreads();
    }
    if (t == 0) g_bsum[b] = sh[0];
}

// per-block prefix of bsum computed locally; then local scan writes rowstart
__global__ void k_rowstart2() {
    __shared__ int sred[256];
    __shared__ int sh[256];
    const int b = blockIdx.x, t = threadIdx.x;
    sred[t] = (t < b) ? g_bsum[t] : 0;   // b <= 195 < 256
    __syncthreads();
#pragma unroll
    for (int off = 128; off; off >>= 1) {
        if (t < off) sred[t] += sred[t + off];
        __syncthreads();
    }
    const int boff = sred[0];

    const int i = b * 256 + t;
    const int v = (i < N_NODES) ? g_deg[i] : 0;
    sh[t] = v;
    __syncthreads();
#pragma unroll
    for (int off = 1; off < 256; off <<= 1) {
        int u = (t >= off) ? sh[t - off] : 0;
        __syncthreads();
        sh[t] += u;
        __syncthreads();
    }
    const int excl = boff + sh[t] - v;
    if (i < N_NODES) {
        g_rowstart[i] = excl;
        g_cursor[i]   = excl;
        if (i == N_NODES - 1) g_rowstart[N_NODES] = excl + v;
    }
}

__global__ void k_scatter() {
    int i = blockIdx.x * blockDim.x + threadIdx.x;
    if (i >= E_TOT) return;
    int s, d;
    if (i < E_EDGES) { s = g_src[i]; d = g_dst[i]; }
    else             { s = d = i - E_EDGES; }
    int pos = atomicAdd(&g_cursor[d], 1);
    g_csr[pos] = s;
}

// ---------------- GEMM1 + fused attention dots ----------------
// Warp-local compute remap: 8 distinct tx x 4 distinct ty per warp
// -> 6 smem wavefronts per warp per kk (was 10) -> fma-issue-bound.
#define BM 128
#define BN 128
#define BK 16
#define APAD 132
__global__ __launch_bounds__(256, 2) void k_gemm1(const float* __restrict__ x,
                                                  const float* __restrict__ W,
                                                  const float* __restrict__ atts,
                                                  const float* __restrict__ attd) {
    __shared__ __align__(16) float As[2][BK][APAD];
    __shared__ __align__(16) float Bs[2][BK][BN];
    const int bm = blockIdx.y * BM, bn = blockIdx.x * BN;
    const int t = threadIdx.x;
    const int w = t >> 5, l = t & 31;
    const int tx = ((w & 1) << 3) | (l & 7);     // 0..15, 8 distinct per warp
    const int ty = ((w >> 1) << 2) | (l >> 3);   // 0..15, 4 distinct per warp
    const int arow0 = t >> 2;
    const int akv   = (t & 3) * 4;
    const int brow0 = t >> 5;
    const int bcv   = (t & 31) * 4;

    unsigned long long acc[8][4];
#pragma unroll
    for (int i = 0; i < 8; i++)
#pragma unroll
        for (int j = 0; j < 4; j++) acc[i][j] = 0ULL;

    float4 pa[2], pb[2];
#pragma unroll
    for (int r = 0; r < 2; r++) {
        int row = arow0 + 64 * r;
        int gr = bm + row;
        pa[r] = make_float4(0.f, 0.f, 0.f, 0.f);
        if (gr < N_NODES) pa[r] = *(const float4*)&x[(size_t)gr * IN_DIM + akv];
        pb[r] = *(const float4*)&W[(size_t)(brow0 + 8 * r) * F1 + bn + bcv];
    }
#pragma unroll
    for (int r = 0; r < 2; r++) {
        int row = arow0 + 64 * r;
        As[0][akv + 0][row] = pa[r].x;
        As[0][akv + 1][row] = pa[r].y;
        As[0][akv + 2][row] = pa[r].z;
        As[0][akv + 3][row] = pa[r].w;
        *(float4*)&Bs[0][brow0 + 8 * r][bcv] = pb[r];
    }
    __syncthreads();

    int buf = 0;
    for (int k0 = 0; k0 < IN_DIM; k0 += BK) {
        const bool has_next = (k0 + BK) < IN_DIM;
        if (has_next) {
#pragma unroll
            for (int r = 0; r < 2; r++) {
                int row = arow0 + 64 * r;
                int gr = bm + row;
                pa[r] = make_float4(0.f, 0.f, 0.f, 0.f);
                if (gr < N_NODES)
                    pa[r] = *(const float4*)&x[(size_t)gr * IN_DIM + k0 + BK + akv];
                pb[r] = *(const float4*)&W[(size_t)(k0 + BK + brow0 + 8 * r) * F1 + bn + bcv];
            }
        }
#pragma unroll
        for (int kk = 0; kk < BK; kk++) {
            ulonglong2 bv0 = *(const ulonglong2*)&Bs[buf][kk][tx * 8];
            ulonglong2 bv1 = *(const ulonglong2*)&Bs[buf][kk][tx * 8 + 4];
            float4 a0 = *(const float4*)&As[buf][kk][ty * 8];
            float4 a1 = *(const float4*)&As[buf][kk][ty * 8 + 4];
            float a[8] = {a0.x, a0.y, a0.z, a0.w, a1.x, a1.y, a1.z, a1.w};
#pragma unroll
            for (int i = 0; i < 8; i++) {
                unsigned long long aa = pk2(a[i], a[i]);
                fma2(acc[i][0], aa, bv0.x);
                fma2(acc[i][1], aa, bv0.y);
                fma2(acc[i][2], aa, bv1.x);
                fma2(acc[i][3], aa, bv1.y);
            }
        }
        if (has_next) {
#pragma unroll
            for (int r = 0; r < 2; r++) {
                int row = arow0 + 64 * r;
                As[buf ^ 1][akv + 0][row] = pa[r].x;
                As[buf ^ 1][akv + 1][row] = pa[r].y;
                As[buf ^ 1][akv + 2][row] = pa[r].z;
                As[buf ^ 1][akv + 3][row] = pa[r].w;
                *(float4*)&Bs[buf ^ 1][brow0 + 8 * r][bcv] = pb[r];
            }
            __syncthreads();
            buf ^= 1;
        }
    }

    // epilogue: store h1 + fused attention partial dots.
    // 8-lane shuffle group = 8 consecutive lanes = 8 distinct tx sharing ty
    // -> covers exactly one 64-col head.
    const int col0 = bn + tx * 8;
    const int head = col0 >> 6;
    float avS[8], avD[8];
#pragma unroll
    for (int j = 0; j < 8; j++) { avS[j] = atts[col0 + j]; avD[j] = attd[col0 + j]; }

#pragma unroll
    for (int i = 0; i < 8; i++) {
        int gr = bm + ty * 8 + i;
        float2 c0 = upk2(acc[i][0]), c1 = upk2(acc[i][1]);
        float2 c2 = upk2(acc[i][2]), c3 = upk2(acc[i][3]);
        float cv[8] = {c0.x, c0.y, c1.x, c1.y, c2.x, c2.y, c3.x, c3.y};
        if (gr < N_NODES) {
            *(float4*)&g_h1[(size_t)gr * F1 + col0]     = make_float4(cv[0], cv[1], cv[2], cv[3]);
            *(float4*)&g_h1[(size_t)gr * F1 + col0 + 4] = make_float4(cv[4], cv[5], cv[6], cv[7]);
        }
        float ps = 0.f, pd = 0.f;
#pragma unroll
        for (int j = 0; j < 8; j++) {
            ps = fmaf(cv[j], avS[j], ps);
            pd = fmaf(cv[j], avD[j], pd);
        }
#pragma unroll
        for (int off = 4; off; off >>= 1) {
            ps += __shfl_down_sync(0xffffffffu, ps, off, 8);
            pd += __shfl_down_sync(0xffffffffu, pd, off, 8);
        }
        if ((l & 7) == 0 && gr < N_NODES) {
            atomicAdd(&g_as1[gr * 4 + head], ps);
            atomicAdd(&g_ad1[gr * 4 + head], pd);
        }
    }
}

// ---------------- layer-1 aggregation: WARP per node ----------------
__global__ __launch_bounds__(256) void k_agg1w(const float* __restrict__ b1) {
    const int node = blockIdx.x * 8 + (threadIdx.x >> 5);  // 6250*8 = 50000 exact
    const int lane = threadIdx.x & 31;
    const int start = g_rowstart[node];
    const int cnt = g_rowstart[node + 1] - start;

    float4 adv = *(const float4*)&g_ad1[node * 4];

    float m0 = NINF, m1 = NINF, m2 = NINF, m3 = NINF;
    for (int e = lane; e < cnt; e += 32) {
        int s = g_csr[start + e];
        float4 av = *(const float4*)&g_as1[s * 4];
        m0 = fmaxf(m0, lrelu(av.x + adv.x));
        m1 = fmaxf(m1, lrelu(av.y + adv.y));
        m2 = fmaxf(m2, lrelu(av.z + adv.z));
        m3 = fmaxf(m3, lrelu(av.w + adv.w));
    }
#pragma unroll
    for (int off = 16; off; off >>= 1) {
        m0 = fmaxf(m0, __shfl_xor_sync(0xffffffffu, m0, off));
        m1 = fmaxf(m1, __shfl_xor_sync(0xffffffffu, m1, off));
        m2 = fmaxf(m2, __shfl_xor_sync(0xffffffffu, m2, off));
        m3 = fmaxf(m3, __shfl_xor_sync(0xffffffffu, m3, off));
    }

    float s0 = 0.f, s1 = 0.f, s2 = 0.f, s3 = 0.f;
    for (int e = lane; e < cnt; e += 32) {
        int s = g_csr[start + e];
        float4 av = *(const float4*)&g_as1[s * 4];
        s0 += expf(lrelu(av.x + adv.x) - m0);
        s1 += expf(lrelu(av.y + adv.y) - m1);
        s2 += expf(lrelu(av.z + adv.z) - m2);
        s3 += expf(lrelu(av.w + adv.w) - m3);
    }
#pragma unroll
    for (int off = 16; off; off >>= 1) {
        s0 += __shfl_xor_sync(0xffffffffu, s0, off);
        s1 += __shfl_xor_sync(0xffffffffu, s1, off);
        s2 += __shfl_xor_sync(0xffffffffu, s2, off);
        s3 += __shfl_xor_sync(0xffffffffu, s3, off);
    }

    const int hh = lane >> 3;
    float advh = (hh == 0) ? adv.x : (hh == 1) ? adv.y : (hh == 2) ? adv.z : adv.w;
    float mh   = (hh == 0) ? m0    : (hh == 1) ? m1    : (hh == 2) ? m2    : m3;
    float sumh = (hh == 0) ? s0    : (hh == 1) ? s1    : (hh == 2) ? s2    : s3;
    const float invh = 1.f / (sumh + 1e-16f);

    float4 a0 = make_float4(0.f, 0.f, 0.f, 0.f);
    float4 a1 = make_float4(0.f, 0.f, 0.f, 0.f);
    const int coff = lane * 8;
    for (int e = 0; e < cnt; e++) {
        int s = g_csr[start + e];
        float av = __ldg(&g_as1[s * 4 + hh]);
        float al = expf(lrelu(av + advh) - mh) * invh;
        const float* row = &g_h1[(size_t)s * F1 + coff];
        float4 v0 = *(const float4*)row;
        float4 v1 = *(const float4*)(row + 4);
        a0.x = fmaf(al, v0.x, a0.x); a0.y = fmaf(al, v0.y, a0.y);
        a0.z = fmaf(al, v0.z, a0.z); a0.w = fmaf(al, v0.w, a0.w);
        a1.x = fmaf(al, v1.x, a1.x); a1.y = fmaf(al, v1.y, a1.y);
        a1.z = fmaf(al, v1.z, a1.z); a1.w = fmaf(al, v1.w, a1.w);
    }

    float4 bb0 = *(const float4*)&b1[coff];
    float4 bb1 = *(const float4*)&b1[coff + 4];
    float r0 = a0.x + bb0.x, r1 = a0.y + bb0.y, r2 = a0.z + bb0.z, r3 = a0.w + bb0.w;
    float r4 = a1.x + bb1.x, r5 = a1.y + bb1.y, r6 = a1.z + bb1.z, r7 = a1.w + bb1.w;
    r0 = r0 > 0.f ? r0 : expm1f(r0); r1 = r1 > 0.f ? r1 : expm1f(r1);
    r2 = r2 > 0.f ? r2 : expm1f(r2); r3 = r3 > 0.f ? r3 : expm1f(r3);
    r4 = r4 > 0.f ? r4 : expm1f(r4); r5 = r5 > 0.f ? r5 : expm1f(r5);
    r6 = r6 > 0.f ? r6 : expm1f(r6); r7 = r7 > 0.f ? r7 : expm1f(r7);
    float* orow = &g_hmid[(size_t)node * F1 + coff];
    *(float4*)orow       = make_float4(r0, r1, r2, r3);
    *(float4*)(orow + 4) = make_float4(r4, r5, r6, r7);
}

// ---------------- GEMM2 + fused attention dots (transposed A, conflict-free) ----
#define BM2 128
#define BK2 32
#define A2PAD 132
__global__ __launch_bounds__(256) void k_gemm2(const float* __restrict__ W2,
                                               const float* __restrict__ atts,
                                               const float* __restrict__ attd) {
    __shared__ __align__(16) float As2t[BK2][A2PAD];
    __shared__ __align__(16) float Ws[BK2][F2];
    const int bm = blockIdx.x * BM2;
    const int t = threadIdx.x;
    const int tx = t & 7;
    const int ty = t >> 3;
    float acc[4][5];
#pragma unroll
    for (int i = 0; i < 4; i++)
#pragma unroll
        for (int j = 0; j < 5; j++) acc[i][j] = 0.f;

    for (int k0 = 0; k0 < F1; k0 += BK2) {
#pragma unroll
        for (int r = 0; r < 4; r++) {
            int f = t + r * 256;
            int row = f >> 3;
            int cv = (f & 7) * 4;
            float4 v = make_float4(0.f, 0.f, 0.f, 0.f);
            int gr = bm + row;
            if (gr < N_NODES) v = *(const float4*)&g_hmid[(size_t)gr * F1 + k0 + cv];
            As2t[cv + 0][row] = v.x;
            As2t[cv + 1][row] = v.y;
            As2t[cv + 2][row] = v.z;
            As2t[cv + 3][row] = v.w;
        }
        for (int idx = t; idx < BK2 * F2; idx += 256) {
            int r = idx / F2, c = idx % F2;
            Ws[r][c] = W2[(size_t)(k0 + r) * F2 + c];
        }
        __syncthreads();
#pragma unroll
        for (int kk = 0; kk < BK2; kk++) {
            float4 a4 = *(const float4*)&As2t[kk][ty * 4];
            float a[4] = {a4.x, a4.y, a4.z, a4.w};
            float b[5];
#pragma unroll
            for (int j = 0; j < 5; j++) b[j] = Ws[kk][tx * 5 + j];
#pragma unroll
            for (int i = 0; i < 4; i++)
#pragma unroll
                for (int j = 0; j < 5; j++) acc[i][j] = fmaf(a[i], b[j], acc[i][j]);
        }
        __syncthreads();
    }

    float avS[5], avD[5];
#pragma unroll
    for (int j = 0; j < 5; j++) { avS[j] = atts[tx * 5 + j]; avD[j] = attd[tx * 5 + j]; }
#pragma unroll
    for (int i = 0; i < 4; i++) {
        int gr = bm + ty * 4 + i;
        if (gr < N_NODES)
#pragma unroll
            for (int j = 0; j < 5; j++)
                g_h2[(size_t)gr * F2 + tx * 5 + j] = acc[i][j];
        float ps = 0.f, pd = 0.f;
#pragma unroll
        for (int j = 0; j < 5; j++) {
            ps = fmaf(acc[i][j], avS[j], ps);
            pd = fmaf(acc[i][j], avD[j], pd);
        }
#pragma unroll
        for (int off = 4; off; off >>= 1) {
            ps += __shfl_down_sync(0xffffffffu, ps, off, 8);
            pd += __shfl_down_sync(0xffffffffu, pd, off, 8);
        }
        if (tx == 0 && gr < N_NODES) { g_as2[gr] = ps; g_ad2[gr] = pd; }
    }
}

// ---------------- layer-2 aggregation + log_softmax: WARP per node ----------------
__global__ __launch_bounds__(256) void k_agg2w(const float* __restrict__ b2,
                                               float* __restrict__ out) {
    const int node = blockIdx.x * 8 + (threadIdx.x >> 5);
    const int lane = threadIdx.x & 31;
    const int start = g_rowstart[node];
    const int cnt = g_rowstart[node + 1] - start;
    const float adv = g_ad2[node];

    float m = NINF;
    for (int e = lane; e < cnt; e += 32)
        m = fmaxf(m, lrelu(g_as2[g_csr[start + e]] + adv));
#pragma unroll
    for (int off = 16; off; off >>= 1)
        m = fmaxf(m, __shfl_xor_sync(0xffffffffu, m, off));

    float se = 0.f;
    for (int e = lane; e < cnt; e += 32)
        se += expf(lrelu(g_as2[g_csr[start + e]] + adv) - m);
#pragma unroll
    for (int off = 16; off; off >>= 1)
        se += __shfl_xor_sync(0xffffffffu, se, off);
    const float inv = 1.f / (se + 1e-16f);

    float a0 = 0.f, a1 = 0.f;
    for (int e = 0; e < cnt; e++) {
        int s = g_csr[start + e];
        float al = expf(lrelu(__ldg(&g_as2[s]) + adv) - m) * inv;
        const float* row = &g_h2[(size_t)s * F2];
        a0 = fmaf(al, row[lane], a0);
        if (lane < 8) a1 = fmaf(al, row[32 + lane], a1);
    }
    float v0 = a0 + b2[lane];
    float v1 = (lane < 8) ? (a1 + b2[32 + lane]) : NINF;

    float mm = fmaxf(v0, v1);
#pragma unroll
    for (int off = 16; off; off >>= 1)
        mm = fmaxf(mm, __shfl_xor_sync(0xffffffffu, mm, off));
    float s2 = expf(v0 - mm) + ((lane < 8) ? expf(v1 - mm) : 0.f);
#pragma unroll
    for (int off = 16; off; off >>= 1)
        s2 += __shfl_xor_sync(0xffffffffu, s2, off);
    const float lg = logf(s2);

    float* orow = &out[(size_t)node * F2];
    orow[lane] = v0 - mm - lg;
    if (lane < 8) orow[32 + lane] = v1 - mm - lg;
}

// ---------------- launch ----------------
extern "C" void kernel_launch(void* const* d_in, const int* in_sizes, int n_in,
                              void* d_out, int out_size) {
    const float* x   = (const float*)d_in[0];
    const void*  ei  = d_in[1];
    const float* W1  = (const float*)d_in[2];
    const float* as1 = (const float*)d_in[3];
    const float* ad1 = (const float*)d_in[4];
    const float* b1  = (const float*)d_in[5];
    const float* W2  = (const float*)d_in[6];
    const float* as2 = (const float*)d_in[7];
    const float* ad2 = (const float*)d_in[8];
    const float* b2  = (const float*)d_in[9];
    float* out = (float*)d_out;

    k_init<<<SCAN_BLOCKS, 256>>>((const int*)ei);            // #1
    k_convert_count<<<(E_EDGES + 255) / 256, 256>>>(ei);     // #2
    k_bsum<<<SCAN_BLOCKS, 256>>>();                          // #3
    dim3 g1(F1 / BN, (N_NODES + BM - 1) / BM);
    k_gemm1<<<g1, 256>>>(x, W1, as1, ad1);                   // #4  <- profiled
    k_rowstart2<<<SCAN_BLOCKS, 256>>>();                     // #5
    k_scatter<<<(E_TOT + 255) / 256, 256>>>();               // #6
    k_agg1w<<<N_NODES / 8, 256>>>(b1);                       // #7
    k_gemm2<<<(N_NODES + BM2 - 1) / BM2, 256>>>(W2, as2, ad2);  // #8
    k_agg2w<<<N_NODES / 8, 256>>>(b2, out);                  // #9
}